// round 3
// baseline (speedup 1.0000x reference)
#include <cuda_runtime.h>
#include <cuda_bf16.h>
#include <cstdint>

#define N_NODES 50000
#define N_EDGES 800000
#define IN_F    256
#define OUT_F   64
#define CAP     96          // per-node bucket capacity (max in-degree ~45)

// Scratch (device globals: allocation-guard compliant, zero-init at load)
__device__ float    g_hw[(size_t)N_NODES * OUT_F];     // projected*norm feats
__device__ int      g_deg[N_NODES];                    // in-degree counters
__device__ int      g_esrc[(size_t)N_NODES * CAP];     // bucketed src ids

// ---------------------------------------------------------------------------
// Bucket fill: g_esrc[d*CAP + slot] = src  (single kernel, no scan needed)
// Requires g_deg == 0 at entry; aggregate_kernel restores that invariant.
// ---------------------------------------------------------------------------
__global__ __launch_bounds__(256) void fill_kernel(
    const int* __restrict__ src,
    const int* __restrict__ dst)
{
    int e = blockIdx.x * blockDim.x + threadIdx.x;
    if (e >= N_EDGES) return;
    int d = dst[e];
    int slot = atomicAdd(&g_deg[d], 1);
    if (slot < CAP) g_esrc[(size_t)d * CAP + slot] = src[e];
}

// ---------------------------------------------------------------------------
// tf32 tensor-core GEMM + fold norm:  g_hw[n,:] = (h[n,:] @ W) * norm[n]
// Block: 128 M-rows x 64 N, 8 warps (each warp: 16 M-rows x 64 N).
// K chunked by 32, mma.sync.m16n8k8 tf32, fp32 accumulate.
// ---------------------------------------------------------------------------
#define ASTRIDE 36   // 32 k + pad, stride % 32 == 4 -> conflict-free frag loads
#define BSTRIDE 72   // 64 n + pad, stride % 32 == 8 -> conflict-free frag loads

__global__ __launch_bounds__(256) void gemm_tf32_kernel(
    const float* __restrict__ h,
    const float* __restrict__ w,
    const float* __restrict__ norm)
{
    __shared__ uint32_t sA[128 * ASTRIDE];  // [row][k]  tf32 bits
    __shared__ uint32_t sB[32 * BSTRIDE];   // [k][n]    tf32 bits

    const int tid  = threadIdx.x;
    const int warp = tid >> 5;
    const int lane = tid & 31;
    const int g    = lane >> 2;   // group id (0..7)
    const int t    = lane & 3;    // thread-in-group (0..3)
    const int row0 = blockIdx.x * 128;

    float acc[8][4];
#pragma unroll
    for (int i = 0; i < 8; i++)
#pragma unroll
        for (int j = 0; j < 4; j++) acc[i][j] = 0.f;

    for (int kk = 0; kk < IN_F; kk += 32) {
        // ---- stage A chunk: 128 rows x 32 k (2 threads per row, 16 floats each)
        {
            const int r    = tid >> 1;
            const int part = tid & 1;
            const int grow = row0 + r;
            const bool ok  = (grow < N_NODES);
            const float* src = h + (size_t)grow * IN_F + kk + part * 16;
#pragma unroll
            for (int i = 0; i < 4; i++) {
                float4 v = ok ? *(const float4*)(src + i * 4)
                              : make_float4(0.f, 0.f, 0.f, 0.f);
                uint32_t u0, u1, u2, u3;
                asm("cvt.rna.tf32.f32 %0, %1;" : "=r"(u0) : "f"(v.x));
                asm("cvt.rna.tf32.f32 %0, %1;" : "=r"(u1) : "f"(v.y));
                asm("cvt.rna.tf32.f32 %0, %1;" : "=r"(u2) : "f"(v.z));
                asm("cvt.rna.tf32.f32 %0, %1;" : "=r"(u3) : "f"(v.w));
                const int c = part * 16 + i * 4;
                sA[r * ASTRIDE + c + 0] = u0;
                sA[r * ASTRIDE + c + 1] = u1;
                sA[r * ASTRIDE + c + 2] = u2;
                sA[r * ASTRIDE + c + 3] = u3;
            }
        }
        // ---- stage B chunk: 32 k-rows x 64 n (8 threads per row, 8 floats each)
        {
            const int r   = tid >> 3;       // k row 0..31
            const int seg = tid & 7;        // 8-float segment
            const float* src = w + (size_t)(kk + r) * OUT_F + seg * 8;
#pragma unroll
            for (int i = 0; i < 2; i++) {
                float4 v = *(const float4*)(src + i * 4);
                uint32_t u0, u1, u2, u3;
                asm("cvt.rna.tf32.f32 %0, %1;" : "=r"(u0) : "f"(v.x));
                asm("cvt.rna.tf32.f32 %0, %1;" : "=r"(u1) : "f"(v.y));
                asm("cvt.rna.tf32.f32 %0, %1;" : "=r"(u2) : "f"(v.z));
                asm("cvt.rna.tf32.f32 %0, %1;" : "=r"(u3) : "f"(v.w));
                const int c = seg * 8 + i * 4;
                sB[r * BSTRIDE + c + 0] = u0;
                sB[r * BSTRIDE + c + 1] = u1;
                sB[r * BSTRIDE + c + 2] = u2;
                sB[r * BSTRIDE + c + 3] = u3;
            }
        }
        __syncthreads();

#pragma unroll
        for (int ks = 0; ks < 4; ks++) {
            const int kb = ks * 8;
            const int arow = warp * 16 + g;
            uint32_t a0 = sA[(arow    ) * ASTRIDE + kb + t    ];
            uint32_t a1 = sA[(arow + 8) * ASTRIDE + kb + t    ];
            uint32_t a2 = sA[(arow    ) * ASTRIDE + kb + t + 4];
            uint32_t a3 = sA[(arow + 8) * ASTRIDE + kb + t + 4];
#pragma unroll
            for (int nt = 0; nt < 8; nt++) {
                uint32_t b0 = sB[(kb + t    ) * BSTRIDE + nt * 8 + g];
                uint32_t b1 = sB[(kb + t + 4) * BSTRIDE + nt * 8 + g];
                asm volatile(
                    "mma.sync.aligned.m16n8k8.row.col.f32.tf32.tf32.f32 "
                    "{%0,%1,%2,%3}, {%4,%5,%6,%7}, {%8,%9}, {%0,%1,%2,%3};"
                    : "+f"(acc[nt][0]), "+f"(acc[nt][1]),
                      "+f"(acc[nt][2]), "+f"(acc[nt][3])
                    : "r"(a0), "r"(a1), "r"(a2), "r"(a3), "r"(b0), "r"(b1));
            }
        }
        __syncthreads();
    }

    // Epilogue: scale by norm[row], write float2 pairs to g_hw
    const int grow0 = row0 + warp * 16 + g;
    const int grow1 = grow0 + 8;
    const bool ok0 = (grow0 < N_NODES);
    const bool ok1 = (grow1 < N_NODES);
    const float nv0 = ok0 ? __ldg(norm + grow0) : 0.f;
    const float nv1 = ok1 ? __ldg(norm + grow1) : 0.f;
#pragma unroll
    for (int nt = 0; nt < 8; nt++) {
        const int c = nt * 8 + 2 * t;
        if (ok0) {
            float2 v = make_float2(acc[nt][0] * nv0, acc[nt][1] * nv0);
            *(float2*)(g_hw + (size_t)grow0 * OUT_F + c) = v;
        }
        if (ok1) {
            float2 v = make_float2(acc[nt][2] * nv1, acc[nt][3] * nv1);
            *(float2*)(g_hw + (size_t)grow1 * OUT_F + c) = v;
        }
    }
}

// ---------------------------------------------------------------------------
// Aggregate: one warp per dst node, lane owns 2 output floats.
// out[d] = relu( (sum over bucket) * norm[d] + bias ).  Also restores
// g_deg[d] = 0 for the next kernel_launch call.
// ---------------------------------------------------------------------------
__global__ __launch_bounds__(256) void aggregate_kernel(
    const float* __restrict__ norm,
    const float* __restrict__ bias,
    float* __restrict__ out)
{
    const int node = (blockIdx.x * 256 + threadIdx.x) >> 5;
    const int lane = threadIdx.x & 31;
    if (node >= N_NODES) return;

    int deg = g_deg[node];               // converged broadcast load
    if (lane == 0) g_deg[node] = 0;      // restore invariant for next call
    deg = min(deg, CAP);

    const int* __restrict__ bucket = g_esrc + (size_t)node * CAP;
    const float2* __restrict__ hw2 = (const float2*)g_hw;

    float ax = 0.f, ay = 0.f;
    int j = 0;
    for (; j + 3 < deg; j += 4) {
        const int s0 = __ldg(bucket + j + 0);
        const int s1 = __ldg(bucket + j + 1);
        const int s2 = __ldg(bucket + j + 2);
        const int s3 = __ldg(bucket + j + 3);
        const float2 v0 = hw2[(size_t)s0 * 32 + lane];
        const float2 v1 = hw2[(size_t)s1 * 32 + lane];
        const float2 v2 = hw2[(size_t)s2 * 32 + lane];
        const float2 v3 = hw2[(size_t)s3 * 32 + lane];
        ax += (v0.x + v1.x) + (v2.x + v3.x);
        ay += (v0.y + v1.y) + (v2.y + v3.y);
    }
    for (; j < deg; j++) {
        const int s0 = __ldg(bucket + j);
        const float2 v0 = hw2[(size_t)s0 * 32 + lane];
        ax += v0.x;
        ay += v0.y;
    }

    const float nv = __ldg(norm + node);
    const float2 b = ((const float2*)bias)[lane];
    float2 r;
    r.x = fmaxf(fmaf(ax, nv, b.x), 0.f);
    r.y = fmaxf(fmaf(ay, nv, b.y), 0.f);
    ((float2*)out)[(size_t)node * 32 + lane] = r;
}

// ---------------------------------------------------------------------------
extern "C" void kernel_launch(void* const* d_in, const int* in_sizes, int n_in,
                              void* d_out, int out_size)
{
    const float* h      = (const float*)d_in[0];
    const float* norm   = (const float*)d_in[1];
    const int*   src    = (const int*)d_in[2];
    const int*   dst    = (const int*)d_in[3];
    const float* weight = (const float*)d_in[4];
    const float* bias   = (const float*)d_in[5];
    float* out = (float*)d_out;

    // 1) projection + fold norm[src] (tensor cores, tf32)
    gemm_tf32_kernel<<<(N_NODES + 127) / 128, 256>>>(h, weight, norm);

    // 2) bucket edges by dst (g_deg is zero on entry; aggregate re-zeroes it)
    fill_kernel<<<(N_EDGES + 255) / 256, 256>>>(src, dst);

    // 3) aggregation + fused epilogue (norm[dst], bias, relu)
    {
        long threads = (long)N_NODES * 32;
        aggregate_kernel<<<(int)((threads + 255) / 256), 256>>>(norm, bias, out);
    }
}

// round 4
// speedup vs baseline: 1.3588x; 1.3588x over previous
#include <cuda_runtime.h>
#include <cuda_bf16.h>
#include <cstdint>

#define N_NODES 50000
#define N_EDGES 800000
#define IN_F    256
#define OUT_F   64
#define N_PAD   50176      // 1024 * 49, padded node count for the scan
#define SCAN_SMEM (N_PAD * 4)

// Scratch (device globals: allocation-guard compliant, zero-init at load)
__device__ float g_hw[(size_t)N_NODES * OUT_F];   // projected*norm features
__device__ int   g_deg[N_NODES];                  // in-degree (zeroed by aggregate)
__device__ int   g_start[N_NODES];                // CSR row starts
__device__ int   g_cursor[N_NODES];               // fill cursors
__device__ int   g_esrc[N_EDGES];                 // src ids bucketed by dst (compact)

// ---------------------------------------------------------------------------
// Histogram: in-degree per dst (g_deg must be 0 at entry; aggregate restores)
// ---------------------------------------------------------------------------
__global__ __launch_bounds__(256) void hist_kernel(const int* __restrict__ dst) {
    int e = blockIdx.x * blockDim.x + threadIdx.x;
    if (e < N_EDGES) atomicAdd(&g_deg[dst[e]], 1);
}

// ---------------------------------------------------------------------------
// Single-block exclusive scan of g_deg -> g_start, g_cursor.
// 50k ints staged through dynamic smem (coalesced), chunked Hillis-Steele.
// ---------------------------------------------------------------------------
__global__ __launch_bounds__(1024) void scan_kernel() {
    extern __shared__ int sh[];          // N_PAD ints
    __shared__ int ssum[1024];
    const int t = threadIdx.x;

    for (int i = t; i < N_PAD; i += 1024)
        sh[i] = (i < N_NODES) ? g_deg[i] : 0;
    __syncthreads();

    const int base = t * 49;
    int s = 0;
#pragma unroll
    for (int i = 0; i < 49; i++) s += sh[base + i];
    ssum[t] = s;
    __syncthreads();

    for (int off = 1; off < 1024; off <<= 1) {
        int x = (t >= off) ? ssum[t - off] : 0;
        __syncthreads();
        ssum[t] += x;
        __syncthreads();
    }

    int run = ssum[t] - s;  // exclusive prefix of this thread's chunk
#pragma unroll
    for (int i = 0; i < 49; i++) {
        int v = sh[base + i];
        sh[base + i] = run;
        run += v;
    }
    __syncthreads();

    for (int i = t; i < N_NODES; i += 1024) {
        int v = sh[i];
        g_start[i]  = v;
        g_cursor[i] = v;
    }
}

// ---------------------------------------------------------------------------
// Bucket fill: compact CSR adjacency
// ---------------------------------------------------------------------------
__global__ __launch_bounds__(256) void fill_kernel(
    const int* __restrict__ src,
    const int* __restrict__ dst)
{
    int e = blockIdx.x * blockDim.x + threadIdx.x;
    if (e >= N_EDGES) return;
    int d = dst[e];
    int slot = atomicAdd(&g_cursor[d], 1);
    g_esrc[slot] = src[e];
}

// ---------------------------------------------------------------------------
// tf32 tensor-core GEMM + fold norm:  g_hw[n,:] = (h[n,:] @ W) * norm[n]
// Block: 128 rows x 64 cols, K chunked by 32, mma.m16n8k8 tf32.
// Software-pipelined: next chunk's LDG issues before this chunk's compute.
// ---------------------------------------------------------------------------
#define ASTRIDE 36   // 32 k + pad (stride%32==4): conflict-free frag loads
#define BSTRIDE 72   // 64 n + pad (stride%32==8): conflict-free frag loads

__global__ __launch_bounds__(256) void gemm_tf32_kernel(
    const float* __restrict__ h,
    const float* __restrict__ w,
    const float* __restrict__ norm)
{
    __shared__ uint32_t sA[128 * ASTRIDE];
    __shared__ uint32_t sB[32 * BSTRIDE];

    const int tid  = threadIdx.x;
    const int warp = tid >> 5;
    const int lane = tid & 31;
    const int g    = lane >> 2;
    const int t    = lane & 3;
    const int row0 = blockIdx.x * 128;

    // staging coordinates
    const int ar   = tid >> 1;          // A row 0..127
    const int ap   = tid & 1;           // half-row (16 floats each)
    const bool aok = (row0 + ar) < N_NODES;
    const float* aptr = h + (size_t)(row0 + ar) * IN_F + ap * 16;
    const int br   = tid >> 3;          // B k-row 0..31
    const int bs   = tid & 7;           // 8-float segment
    const float* bptr = w + (size_t)br * OUT_F + bs * 8;

    float acc[8][4];
#pragma unroll
    for (int i = 0; i < 8; i++)
#pragma unroll
        for (int j = 0; j < 4; j++) acc[i][j] = 0.f;

    float4 aR[4];
    float4 bR[2];

#define LDG_CHUNK(kk)                                                        \
    do {                                                                     \
        _Pragma("unroll")                                                    \
        for (int i = 0; i < 4; i++)                                          \
            aR[i] = aok ? *(const float4*)(aptr + (kk) + i * 4)              \
                        : make_float4(0.f, 0.f, 0.f, 0.f);                   \
        _Pragma("unroll")                                                    \
        for (int i = 0; i < 2; i++)                                          \
            bR[i] = *(const float4*)(bptr + (size_t)(kk) * OUT_F + i * 4);   \
    } while (0)

#define CVT(dst_, src_) asm("cvt.rna.tf32.f32 %0, %1;" : "=r"(dst_) : "f"(src_))

#define STS_CHUNK()                                                          \
    do {                                                                     \
        _Pragma("unroll")                                                    \
        for (int i = 0; i < 4; i++) {                                        \
            uint32_t u0, u1, u2, u3;                                         \
            CVT(u0, aR[i].x); CVT(u1, aR[i].y);                              \
            CVT(u2, aR[i].z); CVT(u3, aR[i].w);                              \
            const int c = ap * 16 + i * 4;                                   \
            sA[ar * ASTRIDE + c + 0] = u0;                                   \
            sA[ar * ASTRIDE + c + 1] = u1;                                   \
            sA[ar * ASTRIDE + c + 2] = u2;                                   \
            sA[ar * ASTRIDE + c + 3] = u3;                                   \
        }                                                                    \
        _Pragma("unroll")                                                    \
        for (int i = 0; i < 2; i++) {                                        \
            uint32_t u0, u1, u2, u3;                                         \
            CVT(u0, bR[i].x); CVT(u1, bR[i].y);                              \
            CVT(u2, bR[i].z); CVT(u3, bR[i].w);                              \
            const int c = bs * 8 + i * 4;                                    \
            sB[br * BSTRIDE + c + 0] = u0;                                   \
            sB[br * BSTRIDE + c + 1] = u1;                                   \
            sB[br * BSTRIDE + c + 2] = u2;                                   \
            sB[br * BSTRIDE + c + 3] = u3;                                   \
        }                                                                    \
    } while (0)

    LDG_CHUNK(0);

    for (int c = 0; c < IN_F / 32; c++) {
        __syncthreads();          // previous compute done -> safe to overwrite
        STS_CHUNK();
        if (c < IN_F / 32 - 1)
            LDG_CHUNK((c + 1) * 32);   // overlap with this chunk's compute
        __syncthreads();

#pragma unroll
        for (int ks = 0; ks < 4; ks++) {
            const int kb = ks * 8;
            const int arow = warp * 16 + g;
            uint32_t a0 = sA[(arow    ) * ASTRIDE + kb + t    ];
            uint32_t a1 = sA[(arow + 8) * ASTRIDE + kb + t    ];
            uint32_t a2 = sA[(arow    ) * ASTRIDE + kb + t + 4];
            uint32_t a3 = sA[(arow + 8) * ASTRIDE + kb + t + 4];
#pragma unroll
            for (int nt = 0; nt < 8; nt++) {
                uint32_t b0 = sB[(kb + t    ) * BSTRIDE + nt * 8 + g];
                uint32_t b1 = sB[(kb + t + 4) * BSTRIDE + nt * 8 + g];
                asm volatile(
                    "mma.sync.aligned.m16n8k8.row.col.f32.tf32.tf32.f32 "
                    "{%0,%1,%2,%3}, {%4,%5,%6,%7}, {%8,%9}, {%0,%1,%2,%3};"
                    : "+f"(acc[nt][0]), "+f"(acc[nt][1]),
                      "+f"(acc[nt][2]), "+f"(acc[nt][3])
                    : "r"(a0), "r"(a1), "r"(a2), "r"(a3), "r"(b0), "r"(b1));
            }
        }
    }

    // Epilogue: scale by norm[row], write float2 pairs
    const int grow0 = row0 + warp * 16 + g;
    const int grow1 = grow0 + 8;
    const bool ok0 = (grow0 < N_NODES);
    const bool ok1 = (grow1 < N_NODES);
    const float nv0 = ok0 ? __ldg(norm + grow0) : 0.f;
    const float nv1 = ok1 ? __ldg(norm + grow1) : 0.f;
#pragma unroll
    for (int nt = 0; nt < 8; nt++) {
        const int c = nt * 8 + 2 * t;
        if (ok0) {
            float2 v = make_float2(acc[nt][0] * nv0, acc[nt][1] * nv0);
            *(float2*)(g_hw + (size_t)grow0 * OUT_F + c) = v;
        }
        if (ok1) {
            float2 v = make_float2(acc[nt][2] * nv1, acc[nt][3] * nv1);
            *(float2*)(g_hw + (size_t)grow1 * OUT_F + c) = v;
        }
    }
}

// ---------------------------------------------------------------------------
// Aggregate: 2 nodes per warp, 16 lanes x float4 per node.
// out[d] = relu( (sum over bucket) * norm[d] + bias ).  Restores g_deg=0.
// ---------------------------------------------------------------------------
__global__ __launch_bounds__(256) void aggregate_kernel(
    const float* __restrict__ norm,
    const float* __restrict__ bias,
    float* __restrict__ out)
{
    const int wid  = (blockIdx.x * 256 + threadIdx.x) >> 5;
    const int lane = threadIdx.x & 31;
    const int half = lane >> 4;
    const int fl   = lane & 15;
    const int node = wid * 2 + half;
    if (node >= N_NODES) return;

    const int start = g_start[node];
    int deg = g_deg[node];
    if (fl == 0) g_deg[node] = 0;          // restore invariant for next call
    const int odeg = __shfl_xor_sync(0xFFFFFFFFu, deg, 16);
    const int maxdeg = deg > odeg ? deg : odeg;

    const int* __restrict__ bk = g_esrc + start;
    const float4* __restrict__ hw4 = (const float4*)g_hw;

    float4 acc = make_float4(0.f, 0.f, 0.f, 0.f);
    int j = 0;
    for (; j + 4 <= maxdeg; j += 4) {
#pragma unroll
        for (int u = 0; u < 4; u++) {
            if (j + u < deg) {
                const int s = __ldg(bk + j + u);
                const float4 v = hw4[(size_t)s * 16 + fl];
                acc.x += v.x; acc.y += v.y; acc.z += v.z; acc.w += v.w;
            }
        }
    }
    for (; j < maxdeg; j++) {
        if (j < deg) {
            const int s = __ldg(bk + j);
            const float4 v = hw4[(size_t)s * 16 + fl];
            acc.x += v.x; acc.y += v.y; acc.z += v.z; acc.w += v.w;
        }
    }

    const float nv = __ldg(norm + node);
    const float4 b = ((const float4*)bias)[fl];
    float4 r;
    r.x = fmaxf(fmaf(acc.x, nv, b.x), 0.f);
    r.y = fmaxf(fmaf(acc.y, nv, b.y), 0.f);
    r.z = fmaxf(fmaf(acc.z, nv, b.z), 0.f);
    r.w = fmaxf(fmaf(acc.w, nv, b.w), 0.f);
    ((float4*)out)[(size_t)node * 16 + fl] = r;
}

// ---------------------------------------------------------------------------
extern "C" void kernel_launch(void* const* d_in, const int* in_sizes, int n_in,
                              void* d_out, int out_size)
{
    const float* h      = (const float*)d_in[0];
    const float* norm   = (const float*)d_in[1];
    const int*   src    = (const int*)d_in[2];
    const int*   dst    = (const int*)d_in[3];
    const float* weight = (const float*)d_in[4];
    const float* bias   = (const float*)d_in[5];
    float* out = (float*)d_out;

    cudaFuncSetAttribute(scan_kernel,
                         cudaFuncAttributeMaxDynamicSharedMemorySize, SCAN_SMEM);

    // 1) projection + fold norm[src] (tensor cores, tf32, pipelined)
    gemm_tf32_kernel<<<(N_NODES + 127) / 128, 256>>>(h, weight, norm);

    // 2) compact CSR build: hist -> single-block scan -> fill
    hist_kernel<<<(N_EDGES + 255) / 256, 256>>>(dst);
    scan_kernel<<<1, 1024, SCAN_SMEM>>>();
    fill_kernel<<<(N_EDGES + 255) / 256, 256>>>(src, dst);

    // 3) aggregation + fused epilogue (norm[dst], bias, relu)
    {
        long warps = (N_NODES + 1) / 2;
        long threads = warps * 32;
        aggregate_kernel<<<(int)((threads + 255) / 256), 256>>>(norm, bias, out);
    }
}

// round 5
// speedup vs baseline: 1.4976x; 1.1021x over previous
#include <cuda_runtime.h>
#include <cuda_bf16.h>
#include <cstdint>

#define N_NODES 50000
#define N_EDGES 800000
#define IN_F    256
#define OUT_F   64
#define N_PAD   50176      // 1024 * 49, padded node count for the scan
#define SCAN_SMEM (N_PAD * 4)

#define GEMM_BLOCKS 391    // ceil(50000/128)
#define HIST_BLOCKS 160
#define E4 (N_EDGES / 4)   // 200000

// Scratch (device globals: allocation-guard compliant, zero-init at load)
__device__ float g_hw[(size_t)N_NODES * OUT_F];   // projected*norm features
__device__ int   g_deg[N_NODES];                  // in-degree (zeroed by aggregate)
__device__ int   g_start[N_NODES];                // CSR row starts
__device__ int   g_slot[N_EDGES];                 // per-edge slot within dst bucket
__device__ int   g_esrc[N_EDGES];                 // src ids bucketed by dst (compact)

// ---------------------------------------------------------------------------
// Fused: tf32 GEMM (+fold norm) on blocks [0, GEMM_BLOCKS) and the in-degree
// histogram (+slot recording) on blocks [GEMM_BLOCKS, GEMM_BLOCKS+HIST_BLOCKS).
// The two roles touch disjoint state; hist latency hides under gemm compute.
// ---------------------------------------------------------------------------
#define ASTRIDE 36   // 32 k + pad (stride%32==4): conflict-free frag loads
#define BSTRIDE 72   // 64 n + pad (stride%32==8): conflict-free frag loads

__global__ __launch_bounds__(256) void gemm_hist_kernel(
    const float* __restrict__ h,
    const float* __restrict__ w,
    const float* __restrict__ norm,
    const int4* __restrict__ dst4)
{
    __shared__ uint32_t sA[128 * ASTRIDE];
    __shared__ uint32_t sB[32 * BSTRIDE];

    const int tid = threadIdx.x;

    // ---------------- histogram role ----------------
    if (blockIdx.x >= GEMM_BLOCKS) {
        int i = (blockIdx.x - GEMM_BLOCKS) * 256 + tid;
        for (; i < E4; i += HIST_BLOCKS * 256) {
            const int4 d = __ldg(dst4 + i);
            int4 sl;
            sl.x = atomicAdd(&g_deg[d.x], 1);
            sl.y = atomicAdd(&g_deg[d.y], 1);
            sl.z = atomicAdd(&g_deg[d.z], 1);
            sl.w = atomicAdd(&g_deg[d.w], 1);
            ((int4*)g_slot)[i] = sl;
        }
        return;
    }

    // ---------------- gemm role ----------------
    const int warp = tid >> 5;
    const int lane = tid & 31;
    const int g    = lane >> 2;
    const int t    = lane & 3;
    const int row0 = blockIdx.x * 128;

    const int ar   = tid >> 1;
    const int ap   = tid & 1;
    const bool aok = (row0 + ar) < N_NODES;
    const float* aptr = h + (size_t)(row0 + ar) * IN_F + ap * 16;
    const int br   = tid >> 3;
    const int bs   = tid & 7;
    const float* bptr = w + (size_t)br * OUT_F + bs * 8;

    float acc[8][4];
#pragma unroll
    for (int i = 0; i < 8; i++)
#pragma unroll
        for (int j = 0; j < 4; j++) acc[i][j] = 0.f;

    float4 aR[4];
    float4 bR[2];

#define LDG_CHUNK(kk)                                                        \
    do {                                                                     \
        _Pragma("unroll")                                                    \
        for (int i = 0; i < 4; i++)                                          \
            aR[i] = aok ? *(const float4*)(aptr + (kk) + i * 4)              \
                        : make_float4(0.f, 0.f, 0.f, 0.f);                   \
        _Pragma("unroll")                                                    \
        for (int i = 0; i < 2; i++)                                          \
            bR[i] = *(const float4*)(bptr + (size_t)(kk) * OUT_F + i * 4);   \
    } while (0)

#define CVT(dst_, src_) asm("cvt.rna.tf32.f32 %0, %1;" : "=r"(dst_) : "f"(src_))

#define STS_CHUNK()                                                          \
    do {                                                                     \
        _Pragma("unroll")                                                    \
        for (int i = 0; i < 4; i++) {                                        \
            uint32_t u0, u1, u2, u3;                                         \
            CVT(u0, aR[i].x); CVT(u1, aR[i].y);                              \
            CVT(u2, aR[i].z); CVT(u3, aR[i].w);                              \
            const int c = ap * 16 + i * 4;                                   \
            sA[ar * ASTRIDE + c + 0] = u0;                                   \
            sA[ar * ASTRIDE + c + 1] = u1;                                   \
            sA[ar * ASTRIDE + c + 2] = u2;                                   \
            sA[ar * ASTRIDE + c + 3] = u3;                                   \
        }                                                                    \
        _Pragma("unroll")                                                    \
        for (int i = 0; i < 2; i++) {                                        \
            uint32_t u0, u1, u2, u3;                                         \
            CVT(u0, bR[i].x); CVT(u1, bR[i].y);                              \
            CVT(u2, bR[i].z); CVT(u3, bR[i].w);                              \
            const int c = bs * 8 + i * 4;                                    \
            sB[br * BSTRIDE + c + 0] = u0;                                   \
            sB[br * BSTRIDE + c + 1] = u1;                                   \
            sB[br * BSTRIDE + c + 2] = u2;                                   \
            sB[br * BSTRIDE + c + 3] = u3;                                   \
        }                                                                    \
    } while (0)

    LDG_CHUNK(0);

    for (int c = 0; c < IN_F / 32; c++) {
        __syncthreads();
        STS_CHUNK();
        if (c < IN_F / 32 - 1)
            LDG_CHUNK((c + 1) * 32);
        __syncthreads();

#pragma unroll
        for (int ks = 0; ks < 4; ks++) {
            const int kb = ks * 8;
            const int arow = warp * 16 + g;
            uint32_t a0 = sA[(arow    ) * ASTRIDE + kb + t    ];
            uint32_t a1 = sA[(arow + 8) * ASTRIDE + kb + t    ];
            uint32_t a2 = sA[(arow    ) * ASTRIDE + kb + t + 4];
            uint32_t a3 = sA[(arow + 8) * ASTRIDE + kb + t + 4];
#pragma unroll
            for (int nt = 0; nt < 8; nt++) {
                uint32_t b0 = sB[(kb + t    ) * BSTRIDE + nt * 8 + g];
                uint32_t b1 = sB[(kb + t + 4) * BSTRIDE + nt * 8 + g];
                asm volatile(
                    "mma.sync.aligned.m16n8k8.row.col.f32.tf32.tf32.f32 "
                    "{%0,%1,%2,%3}, {%4,%5,%6,%7}, {%8,%9}, {%0,%1,%2,%3};"
                    : "+f"(acc[nt][0]), "+f"(acc[nt][1]),
                      "+f"(acc[nt][2]), "+f"(acc[nt][3])
                    : "r"(a0), "r"(a1), "r"(a2), "r"(a3), "r"(b0), "r"(b1));
            }
        }
    }

    const int grow0 = row0 + warp * 16 + g;
    const int grow1 = grow0 + 8;
    const bool ok0 = (grow0 < N_NODES);
    const bool ok1 = (grow1 < N_NODES);
    const float nv0 = ok0 ? __ldg(norm + grow0) : 0.f;
    const float nv1 = ok1 ? __ldg(norm + grow1) : 0.f;
#pragma unroll
    for (int nt = 0; nt < 8; nt++) {
        const int c = nt * 8 + 2 * t;
        if (ok0) {
            float2 v = make_float2(acc[nt][0] * nv0, acc[nt][1] * nv0);
            *(float2*)(g_hw + (size_t)grow0 * OUT_F + c) = v;
        }
        if (ok1) {
            float2 v = make_float2(acc[nt][2] * nv1, acc[nt][3] * nv1);
            *(float2*)(g_hw + (size_t)grow1 * OUT_F + c) = v;
        }
    }
}

// ---------------------------------------------------------------------------
// Single-block exclusive scan of g_deg -> g_start.
// ---------------------------------------------------------------------------
__global__ __launch_bounds__(1024) void scan_kernel() {
    extern __shared__ int sh[];          // N_PAD ints
    __shared__ int ssum[1024];
    const int t = threadIdx.x;

    for (int i = t; i < N_PAD; i += 1024)
        sh[i] = (i < N_NODES) ? g_deg[i] : 0;
    __syncthreads();

    const int base = t * 49;
    int s = 0;
#pragma unroll
    for (int i = 0; i < 49; i++) s += sh[base + i];
    ssum[t] = s;
    __syncthreads();

    for (int off = 1; off < 1024; off <<= 1) {
        int x = (t >= off) ? ssum[t - off] : 0;
        __syncthreads();
        ssum[t] += x;
        __syncthreads();
    }

    int run = ssum[t] - s;
#pragma unroll
    for (int i = 0; i < 49; i++) {
        int v = sh[base + i];
        sh[base + i] = run;
        run += v;
    }
    __syncthreads();

    for (int i = t; i < N_NODES; i += 1024)
        g_start[i] = sh[i];
}

// ---------------------------------------------------------------------------
// Atomic-free fill: g_esrc[g_start[dst] + slot] = src   (4 edges per thread)
// ---------------------------------------------------------------------------
__global__ __launch_bounds__(256) void fill_kernel(
    const int4* __restrict__ src4,
    const int4* __restrict__ dst4)
{
    const int i = blockIdx.x * 256 + threadIdx.x;
    if (i >= E4) return;
    const int4 d  = __ldg(dst4 + i);
    const int4 sl = ((const int4*)g_slot)[i];
    const int4 s  = __ldg(src4 + i);
    g_esrc[g_start[d.x] + sl.x] = s.x;
    g_esrc[g_start[d.y] + sl.y] = s.y;
    g_esrc[g_start[d.z] + sl.z] = s.z;
    g_esrc[g_start[d.w] + sl.w] = s.w;
}

// ---------------------------------------------------------------------------
// Aggregate: 2 nodes per warp, 16 lanes x float4 per node.
// Indices fetched 16-at-a-time (coalesced) and shuffle-broadcast, so the
// 16 gather LDG.128s per batch issue back-to-back (high MLP).
// Restores g_deg = 0 for the next kernel_launch call.
// ---------------------------------------------------------------------------
__global__ __launch_bounds__(256) void aggregate_kernel(
    const float* __restrict__ norm,
    const float* __restrict__ bias,
    float* __restrict__ out)
{
    const int wid  = (blockIdx.x * 256 + threadIdx.x) >> 5;
    const int lane = threadIdx.x & 31;
    const int half = lane & 16;          // 0 or 16
    const int fl   = lane & 15;
    const int node = wid * 2 + (half >> 4);
    if (node >= N_NODES) return;         // N_NODES even: uniform per warp

    const int start = g_start[node];
    int deg = g_deg[node];
    if (fl == 0) g_deg[node] = 0;        // restore invariant for next call
    const int odeg = __shfl_xor_sync(0xFFFFFFFFu, deg, 16);
    const int maxdeg = deg > odeg ? deg : odeg;

    const int* __restrict__ bk = g_esrc + start;
    const float4* __restrict__ hw4 = (const float4*)g_hw;

    float4 acc = make_float4(0.f, 0.f, 0.f, 0.f);
    for (int b = 0; b < maxdeg; b += 16) {
        const int idx = (b + fl < deg) ? __ldg(bk + b + fl) : 0;
#pragma unroll
        for (int j = 0; j < 16; j++) {
            const int s = __shfl_sync(0xFFFFFFFFu, idx, half + j);
            if (b + j < deg) {
                const float4 v = __ldg(hw4 + (size_t)s * 16 + fl);
                acc.x += v.x; acc.y += v.y; acc.z += v.z; acc.w += v.w;
            }
        }
    }

    const float nv = __ldg(norm + node);
    const float4 bia = ((const float4*)bias)[fl];
    float4 r;
    r.x = fmaxf(fmaf(acc.x, nv, bia.x), 0.f);
    r.y = fmaxf(fmaf(acc.y, nv, bia.y), 0.f);
    r.z = fmaxf(fmaf(acc.z, nv, bia.z), 0.f);
    r.w = fmaxf(fmaf(acc.w, nv, bia.w), 0.f);
    ((float4*)out)[(size_t)node * 16 + fl] = r;
}

// ---------------------------------------------------------------------------
extern "C" void kernel_launch(void* const* d_in, const int* in_sizes, int n_in,
                              void* d_out, int out_size)
{
    const float* h      = (const float*)d_in[0];
    const float* norm   = (const float*)d_in[1];
    const int*   src    = (const int*)d_in[2];
    const int*   dst    = (const int*)d_in[3];
    const float* weight = (const float*)d_in[4];
    const float* bias   = (const float*)d_in[5];
    float* out = (float*)d_out;

    cudaFuncSetAttribute(scan_kernel,
                         cudaFuncAttributeMaxDynamicSharedMemorySize, SCAN_SMEM);

    // 1) fused projection (tf32 TC) + in-degree histogram w/ slot recording
    gemm_hist_kernel<<<GEMM_BLOCKS + HIST_BLOCKS, 256>>>(
        h, weight, norm, (const int4*)dst);

    // 2) exclusive scan -> CSR starts
    scan_kernel<<<1, 1024, SCAN_SMEM>>>();

    // 3) atomic-free bucket fill
    fill_kernel<<<(E4 + 255) / 256, 256>>>((const int4*)src, (const int4*)dst);

    // 4) aggregation + fused epilogue (norm[dst], bias, relu)
    aggregate_kernel<<<(N_NODES / 2 * 32) / 256, 256>>>(norm, bias, out);
}

// round 6
// speedup vs baseline: 1.5094x; 1.0079x over previous
#include <cuda_runtime.h>
#include <cuda_bf16.h>
#include <cstdint>

#define N_NODES 50000
#define N_EDGES 800000
#define IN_F    256
#define OUT_F   64
#define N_PAD   50176      // 1024 * 49, padded node count for the scan
#define SCAN_SMEM (N_PAD * 4)
#define E4 (N_EDGES / 4)   // 200000
#define GEMM_BLOCKS 782    // ceil(50000/64)

// Scratch (device globals: allocation-guard compliant, zero-init at load)
__device__ float g_hw[(size_t)N_NODES * OUT_F];   // projected*norm features
__device__ int   g_deg[N_NODES];                  // in-degree (zeroed by aggregate)
__device__ int   g_start[N_NODES];                // CSR row starts
__device__ int   g_slot[N_EDGES];                 // per-edge slot within dst bucket
__device__ int   g_esrc[N_EDGES];                 // src ids bucketed by dst

// ---------------------------------------------------------------------------
// Histogram + slot recording (runs on side stream, concurrent with GEMM)
// ---------------------------------------------------------------------------
__global__ __launch_bounds__(256) void hist_kernel(const int4* __restrict__ dst4) {
    const int i = blockIdx.x * 256 + threadIdx.x;
    if (i >= E4) return;
    const int4 d = __ldg(dst4 + i);
    int4 sl;
    sl.x = atomicAdd(&g_deg[d.x], 1);
    sl.y = atomicAdd(&g_deg[d.y], 1);
    sl.z = atomicAdd(&g_deg[d.z], 1);
    sl.w = atomicAdd(&g_deg[d.w], 1);
    ((int4*)g_slot)[i] = sl;
}

// ---------------------------------------------------------------------------
// Single-block exclusive scan of g_deg -> g_start
// ---------------------------------------------------------------------------
__global__ __launch_bounds__(1024) void scan_kernel() {
    extern __shared__ int sh[];          // N_PAD ints
    __shared__ int ssum[1024];
    const int t = threadIdx.x;

    for (int i = t; i < N_PAD; i += 1024)
        sh[i] = (i < N_NODES) ? g_deg[i] : 0;
    __syncthreads();

    const int base = t * 49;
    int s = 0;
#pragma unroll
    for (int i = 0; i < 49; i++) s += sh[base + i];
    ssum[t] = s;
    __syncthreads();

    for (int off = 1; off < 1024; off <<= 1) {
        int x = (t >= off) ? ssum[t - off] : 0;
        __syncthreads();
        ssum[t] += x;
        __syncthreads();
    }

    int run = ssum[t] - s;
#pragma unroll
    for (int i = 0; i < 49; i++) {
        int v = sh[base + i];
        sh[base + i] = run;
        run += v;
    }
    __syncthreads();

    for (int i = t; i < N_NODES; i += 1024)
        g_start[i] = sh[i];
}

// ---------------------------------------------------------------------------
// Atomic-free fill: g_esrc[g_start[dst] + slot] = src   (4 edges per thread)
// ---------------------------------------------------------------------------
__global__ __launch_bounds__(256) void fill_kernel(
    const int4* __restrict__ src4,
    const int4* __restrict__ dst4)
{
    const int i = blockIdx.x * 256 + threadIdx.x;
    if (i >= E4) return;
    const int4 d  = __ldg(dst4 + i);
    const int4 sl = ((const int4*)g_slot)[i];
    const int4 s  = __ldg(src4 + i);
    g_esrc[g_start[d.x] + sl.x] = s.x;
    g_esrc[g_start[d.y] + sl.y] = s.y;
    g_esrc[g_start[d.z] + sl.z] = s.z;
    g_esrc[g_start[d.w] + sl.w] = s.w;
}

// ---------------------------------------------------------------------------
// tf32 tensor-core GEMM + fold norm:  g_hw[n,:] = (h[n,:] @ W) * norm[n]
// 64 rows x 64 cols per block, 128 threads (4 warps), K chunked by 32.
// Software-pipelined LDG; 782 blocks for good occupancy + small tail.
// ---------------------------------------------------------------------------
#define ASTRIDE 36   // 32 k + pad (stride%32==4): conflict-free frag loads
#define BSTRIDE 72   // 64 n + pad (stride%32==8): conflict-free frag loads

__global__ __launch_bounds__(128) void gemm_tf32_kernel(
    const float* __restrict__ h,
    const float* __restrict__ w,
    const float* __restrict__ norm)
{
    __shared__ uint32_t sA[64 * ASTRIDE];
    __shared__ uint32_t sB[32 * BSTRIDE];

    const int tid  = threadIdx.x;
    const int warp = tid >> 5;      // 0..3
    const int lane = tid & 31;
    const int g    = lane >> 2;
    const int t    = lane & 3;
    const int row0 = blockIdx.x * 64;

    const int ar   = tid >> 1;      // A row 0..63
    const int ap   = tid & 1;       // half-row (16 floats)
    const bool aok = (row0 + ar) < N_NODES;
    const float* aptr = h + (size_t)(row0 + ar) * IN_F + ap * 16;
    const int br   = tid >> 2;      // B k-row 0..31
    const int bs   = tid & 3;       // 16-float segment
    const float* bptr = w + (size_t)br * OUT_F + bs * 16;

    float acc[8][4];
#pragma unroll
    for (int i = 0; i < 8; i++)
#pragma unroll
        for (int j = 0; j < 4; j++) acc[i][j] = 0.f;

    float4 aR[4];
    float4 bR[4];

#define LDG_CHUNK(kk)                                                        \
    do {                                                                     \
        _Pragma("unroll")                                                    \
        for (int i = 0; i < 4; i++)                                          \
            aR[i] = aok ? *(const float4*)(aptr + (kk) + i * 4)              \
                        : make_float4(0.f, 0.f, 0.f, 0.f);                   \
        _Pragma("unroll")                                                    \
        for (int i = 0; i < 4; i++)                                          \
            bR[i] = *(const float4*)(bptr + (size_t)(kk) * OUT_F + i * 4);   \
    } while (0)

#define CVT(dst_, src_) asm("cvt.rna.tf32.f32 %0, %1;" : "=r"(dst_) : "f"(src_))

#define STS_CHUNK()                                                          \
    do {                                                                     \
        _Pragma("unroll")                                                    \
        for (int i = 0; i < 4; i++) {                                        \
            uint32_t u0, u1, u2, u3;                                         \
            CVT(u0, aR[i].x); CVT(u1, aR[i].y);                              \
            CVT(u2, aR[i].z); CVT(u3, aR[i].w);                              \
            const int c = ap * 16 + i * 4;                                   \
            sA[ar * ASTRIDE + c + 0] = u0;                                   \
            sA[ar * ASTRIDE + c + 1] = u1;                                   \
            sA[ar * ASTRIDE + c + 2] = u2;                                   \
            sA[ar * ASTRIDE + c + 3] = u3;                                   \
        }                                                                    \
        _Pragma("unroll")                                                    \
        for (int i = 0; i < 4; i++) {                                        \
            uint32_t u0, u1, u2, u3;                                         \
            CVT(u0, bR[i].x); CVT(u1, bR[i].y);                              \
            CVT(u2, bR[i].z); CVT(u3, bR[i].w);                              \
            const int c = bs * 16 + i * 4;                                   \
            sB[br * BSTRIDE + c + 0] = u0;                                   \
            sB[br * BSTRIDE + c + 1] = u1;                                   \
            sB[br * BSTRIDE + c + 2] = u2;                                   \
            sB[br * BSTRIDE + c + 3] = u3;                                   \
        }                                                                    \
    } while (0)

    LDG_CHUNK(0);

    for (int c = 0; c < IN_F / 32; c++) {
        __syncthreads();
        STS_CHUNK();
        if (c < IN_F / 32 - 1)
            LDG_CHUNK((c + 1) * 32);
        __syncthreads();

#pragma unroll
        for (int ks = 0; ks < 4; ks++) {
            const int kb = ks * 8;
            const int arow = warp * 16 + g;
            uint32_t a0 = sA[(arow    ) * ASTRIDE + kb + t    ];
            uint32_t a1 = sA[(arow + 8) * ASTRIDE + kb + t    ];
            uint32_t a2 = sA[(arow    ) * ASTRIDE + kb + t + 4];
            uint32_t a3 = sA[(arow + 8) * ASTRIDE + kb + t + 4];
#pragma unroll
            for (int nt = 0; nt < 8; nt++) {
                uint32_t b0 = sB[(kb + t    ) * BSTRIDE + nt * 8 + g];
                uint32_t b1 = sB[(kb + t + 4) * BSTRIDE + nt * 8 + g];
                asm volatile(
                    "mma.sync.aligned.m16n8k8.row.col.f32.tf32.tf32.f32 "
                    "{%0,%1,%2,%3}, {%4,%5,%6,%7}, {%8,%9}, {%0,%1,%2,%3};"
                    : "+f"(acc[nt][0]), "+f"(acc[nt][1]),
                      "+f"(acc[nt][2]), "+f"(acc[nt][3])
                    : "r"(a0), "r"(a1), "r"(a2), "r"(a3), "r"(b0), "r"(b1));
            }
        }
    }

    const int grow0 = row0 + warp * 16 + g;
    const int grow1 = grow0 + 8;
    const bool ok0 = (grow0 < N_NODES);
    const bool ok1 = (grow1 < N_NODES);
    const float nv0 = ok0 ? __ldg(norm + grow0) : 0.f;
    const float nv1 = ok1 ? __ldg(norm + grow1) : 0.f;
#pragma unroll
    for (int nt = 0; nt < 8; nt++) {
        const int c = nt * 8 + 2 * t;
        if (ok0) {
            float2 v = make_float2(acc[nt][0] * nv0, acc[nt][1] * nv0);
            *(float2*)(g_hw + (size_t)grow0 * OUT_F + c) = v;
        }
        if (ok1) {
            float2 v = make_float2(acc[nt][2] * nv1, acc[nt][3] * nv1);
            *(float2*)(g_hw + (size_t)grow1 * OUT_F + c) = v;
        }
    }
}

// ---------------------------------------------------------------------------
// Aggregate: 4 nodes per warp (two interleaved node-pairs), 16 lanes x float4
// per node.  32 independent gather LDG.128s in flight per warp batch.
// Restores g_deg = 0 for the next kernel_launch call.
// ---------------------------------------------------------------------------
__global__ __launch_bounds__(256) void aggregate_kernel(
    const float* __restrict__ norm,
    const float* __restrict__ bias,
    float* __restrict__ out)
{
    const unsigned FULL = 0xFFFFFFFFu;
    const int wid  = (blockIdx.x * 256 + threadIdx.x) >> 5;
    const int base = wid * 4;
    if (base >= N_NODES) return;         // N_NODES % 4 == 0: uniform per warp
    const int lane = threadIdx.x & 31;
    const int half = lane >> 4;          // 0 or 1
    const int fl   = lane & 15;

    int st = 0, dg = 0;
    if (lane < 4) {
        st = g_start[base + lane];
        dg = g_deg[base + lane];
        g_deg[base + lane] = 0;          // restore invariant for next call
    }
    const int stA = __shfl_sync(FULL, st, half);
    const int dgA = __shfl_sync(FULL, dg, half);
    const int stB = __shfl_sync(FULL, st, 2 + half);
    const int dgB = __shfl_sync(FULL, dg, 2 + half);
    const int d0 = __shfl_sync(FULL, dg, 0), d1 = __shfl_sync(FULL, dg, 1);
    const int d2 = __shfl_sync(FULL, dg, 2), d3 = __shfl_sync(FULL, dg, 3);
    int m = max(max(d0, d1), max(d2, d3));

    const float4* __restrict__ hw4 = (const float4*)g_hw;

    float4 aA = make_float4(0.f, 0.f, 0.f, 0.f);
    float4 aB = make_float4(0.f, 0.f, 0.f, 0.f);

    for (int b = 0; b < m; b += 16) {
        const int iA = (b + fl < dgA) ? __ldg(g_esrc + stA + b + fl) : 0;
        const int iB = (b + fl < dgB) ? __ldg(g_esrc + stB + b + fl) : 0;
#pragma unroll
        for (int j = 0; j < 16; j++) {
            const int sa = __shfl_sync(FULL, iA, (half << 4) + j);
            const int sb = __shfl_sync(FULL, iB, (half << 4) + j);
            if (b + j < dgA) {
                const float4 v = __ldg(hw4 + (size_t)sa * 16 + fl);
                aA.x += v.x; aA.y += v.y; aA.z += v.z; aA.w += v.w;
            }
            if (b + j < dgB) {
                const float4 v = __ldg(hw4 + (size_t)sb * 16 + fl);
                aB.x += v.x; aB.y += v.y; aB.z += v.z; aB.w += v.w;
            }
        }
    }

    const int nodeA = base + half;
    const int nodeB = base + 2 + half;
    const float nA = __ldg(norm + nodeA);
    const float nB = __ldg(norm + nodeB);
    const float4 bi = ((const float4*)bias)[fl];
    float4 rA, rB;
    rA.x = fmaxf(fmaf(aA.x, nA, bi.x), 0.f);
    rA.y = fmaxf(fmaf(aA.y, nA, bi.y), 0.f);
    rA.z = fmaxf(fmaf(aA.z, nA, bi.z), 0.f);
    rA.w = fmaxf(fmaf(aA.w, nA, bi.w), 0.f);
    rB.x = fmaxf(fmaf(aB.x, nB, bi.x), 0.f);
    rB.y = fmaxf(fmaf(aB.y, nB, bi.y), 0.f);
    rB.z = fmaxf(fmaf(aB.z, nB, bi.z), 0.f);
    rB.w = fmaxf(fmaf(aB.w, nB, bi.w), 0.f);
    ((float4*)out)[(size_t)nodeA * 16 + fl] = rA;
    ((float4*)out)[(size_t)nodeB * 16 + fl] = rB;
}

// ---------------------------------------------------------------------------
extern "C" void kernel_launch(void* const* d_in, const int* in_sizes, int n_in,
                              void* d_out, int out_size)
{
    const float* h      = (const float*)d_in[0];
    const float* norm   = (const float*)d_in[1];
    const int*   src    = (const int*)d_in[2];
    const int*   dst    = (const int*)d_in[3];
    const float* weight = (const float*)d_in[4];
    const float* bias   = (const float*)d_in[5];
    float* out = (float*)d_out;

    // Host-side resources, created once; device work is identical every call.
    static cudaStream_t sB = nullptr;
    static cudaEvent_t  evFork = nullptr, evJoin = nullptr;
    if (sB == nullptr) {
        cudaStreamCreateWithFlags(&sB, cudaStreamNonBlocking);
        cudaEventCreateWithFlags(&evFork, cudaEventDisableTiming);
        cudaEventCreateWithFlags(&evJoin, cudaEventDisableTiming);
        cudaFuncSetAttribute(scan_kernel,
                             cudaFuncAttributeMaxDynamicSharedMemorySize,
                             SCAN_SMEM);
    }

    // Fork: CSR build on side stream, concurrent with the GEMM.
    cudaEventRecord(evFork, 0);
    cudaStreamWaitEvent(sB, evFork, 0);
    hist_kernel<<<(E4 + 255) / 256, 256, 0, sB>>>((const int4*)dst);
    scan_kernel<<<1, 1024, SCAN_SMEM, sB>>>();
    fill_kernel<<<(E4 + 255) / 256, 256, 0, sB>>>((const int4*)src,
                                                  (const int4*)dst);
    cudaEventRecord(evJoin, sB);

    // GEMM on the main stream (runs concurrent with CSR build).
    gemm_tf32_kernel<<<GEMM_BLOCKS, 128>>>(h, weight, norm);

    // Join, then aggregate (+ fused norm/bias/relu epilogue).
    cudaStreamWaitEvent(0, evJoin, 0);
    {
        const int warps  = N_NODES / 4;          // 12500
        const int blocks = (warps * 32 + 255) / 256;
        aggregate_kernel<<<blocks, 256>>>(norm, bias, out);
    }
}

// round 7
// speedup vs baseline: 1.8979x; 1.2574x over previous
#include <cuda_runtime.h>
#include <cuda_fp16.h>
#include <cstdint>

#define N_NODES 50000
#define N_EDGES 800000
#define IN_F    256
#define OUT_F   64
#define N_PAD   50176      // 1024 * 49, padded node count for the scan
#define SCAN_SMEM (N_PAD * 4)
#define E4 (N_EDGES / 4)   // 200000
#define GEMM_BLOCKS 391    // ceil(50000/128)

// Scratch (device globals: allocation-guard compliant, zero-init at load)
__device__ __half g_hw[(size_t)N_NODES * OUT_F];  // projected*norm feats (fp16)
__device__ int    g_deg[N_NODES];                 // in-degree (zeroed by aggregate)
__device__ int    g_start[N_NODES];               // CSR row starts
__device__ int    g_slot[N_EDGES];                // per-edge slot within dst bucket
__device__ int    g_esrc[N_EDGES];                // src ids bucketed by dst

// ---------------------------------------------------------------------------
// Histogram + slot recording (side stream, concurrent with GEMM)
// ---------------------------------------------------------------------------
__global__ __launch_bounds__(256) void hist_kernel(const int4* __restrict__ dst4) {
    const int i = blockIdx.x * 256 + threadIdx.x;
    if (i >= E4) return;
    const int4 d = __ldg(dst4 + i);
    int4 sl;
    sl.x = atomicAdd(&g_deg[d.x], 1);
    sl.y = atomicAdd(&g_deg[d.y], 1);
    sl.z = atomicAdd(&g_deg[d.z], 1);
    sl.w = atomicAdd(&g_deg[d.w], 1);
    ((int4*)g_slot)[i] = sl;
}

// ---------------------------------------------------------------------------
// Single-block exclusive scan of g_deg -> g_start
// ---------------------------------------------------------------------------
__global__ __launch_bounds__(1024) void scan_kernel() {
    extern __shared__ int sh[];          // N_PAD ints
    __shared__ int ssum[1024];
    const int t = threadIdx.x;

    for (int i = t; i < N_PAD; i += 1024)
        sh[i] = (i < N_NODES) ? g_deg[i] : 0;
    __syncthreads();

    const int base = t * 49;
    int s = 0;
#pragma unroll
    for (int i = 0; i < 49; i++) s += sh[base + i];
    ssum[t] = s;
    __syncthreads();

    for (int off = 1; off < 1024; off <<= 1) {
        int x = (t >= off) ? ssum[t - off] : 0;
        __syncthreads();
        ssum[t] += x;
        __syncthreads();
    }

    int run = ssum[t] - s;
#pragma unroll
    for (int i = 0; i < 49; i++) {
        int v = sh[base + i];
        sh[base + i] = run;
        run += v;
    }
    __syncthreads();

    for (int i = t; i < N_NODES; i += 1024)
        g_start[i] = sh[i];
}

// ---------------------------------------------------------------------------
// Atomic-free fill: g_esrc[g_start[dst] + slot] = src   (4 edges per thread)
// ---------------------------------------------------------------------------
__global__ __launch_bounds__(256) void fill_kernel(
    const int4* __restrict__ src4,
    const int4* __restrict__ dst4)
{
    const int i = blockIdx.x * 256 + threadIdx.x;
    if (i >= E4) return;
    const int4 d  = __ldg(dst4 + i);
    const int4 sl = ((const int4*)g_slot)[i];
    const int4 s  = __ldg(src4 + i);
    g_esrc[g_start[d.x] + sl.x] = s.x;
    g_esrc[g_start[d.y] + sl.y] = s.y;
    g_esrc[g_start[d.z] + sl.z] = s.z;
    g_esrc[g_start[d.w] + sl.w] = s.w;
}

// ---------------------------------------------------------------------------
// tf32 tensor-core GEMM + fold norm:  g_hw[n,:] = fp16( (h[n,:] @ W) * norm[n] )
// 128 rows x 64 cols per block, 256 threads, K chunked by 32, pipelined LDG.
// ---------------------------------------------------------------------------
#define ASTRIDE 36   // 32 k + pad (stride%32==4): conflict-free frag loads
#define BSTRIDE 72   // 64 n + pad (stride%32==8): conflict-free frag loads

__global__ __launch_bounds__(256) void gemm_tf32_kernel(
    const float* __restrict__ h,
    const float* __restrict__ w,
    const float* __restrict__ norm)
{
    __shared__ uint32_t sA[128 * ASTRIDE];
    __shared__ uint32_t sB[32 * BSTRIDE];

    const int tid  = threadIdx.x;
    const int warp = tid >> 5;
    const int lane = tid & 31;
    const int g    = lane >> 2;
    const int t    = lane & 3;
    const int row0 = blockIdx.x * 128;

    const int ar   = tid >> 1;          // A row 0..127
    const int ap   = tid & 1;           // half-row (16 floats)
    const bool aok = (row0 + ar) < N_NODES;
    const float* aptr = h + (size_t)(row0 + ar) * IN_F + ap * 16;
    const int br   = tid >> 3;          // B k-row 0..31
    const int bs   = tid & 7;           // 8-float segment
    const float* bptr = w + (size_t)br * OUT_F + bs * 8;

    float acc[8][4];
#pragma unroll
    for (int i = 0; i < 8; i++)
#pragma unroll
        for (int j = 0; j < 4; j++) acc[i][j] = 0.f;

    float4 aR[4];
    float4 bR[2];

#define LDG_CHUNK(kk)                                                        \
    do {                                                                     \
        _Pragma("unroll")                                                    \
        for (int i = 0; i < 4; i++)                                          \
            aR[i] = aok ? *(const float4*)(aptr + (kk) + i * 4)              \
                        : make_float4(0.f, 0.f, 0.f, 0.f);                   \
        _Pragma("unroll")                                                    \
        for (int i = 0; i < 2; i++)                                          \
            bR[i] = *(const float4*)(bptr + (size_t)(kk) * OUT_F + i * 4);   \
    } while (0)

#define CVT(dst_, src_) asm("cvt.rna.tf32.f32 %0, %1;" : "=r"(dst_) : "f"(src_))

#define STS_CHUNK()                                                          \
    do {                                                                     \
        _Pragma("unroll")                                                    \
        for (int i = 0; i < 4; i++) {                                        \
            uint32_t u0, u1, u2, u3;                                         \
            CVT(u0, aR[i].x); CVT(u1, aR[i].y);                              \
            CVT(u2, aR[i].z); CVT(u3, aR[i].w);                              \
            const int c = ap * 16 + i * 4;                                   \
            sA[ar * ASTRIDE + c + 0] = u0;                                   \
            sA[ar * ASTRIDE + c + 1] = u1;                                   \
            sA[ar * ASTRIDE + c + 2] = u2;                                   \
            sA[ar * ASTRIDE + c + 3] = u3;                                   \
        }                                                                    \
        _Pragma("unroll")                                                    \
        for (int i = 0; i < 2; i++) {                                        \
            uint32_t u0, u1, u2, u3;                                         \
            CVT(u0, bR[i].x); CVT(u1, bR[i].y);                              \
            CVT(u2, bR[i].z); CVT(u3, bR[i].w);                              \
            const int c = bs * 8 + i * 4;                                    \
            sB[br * BSTRIDE + c + 0] = u0;                                   \
            sB[br * BSTRIDE + c + 1] = u1;                                   \
            sB[br * BSTRIDE + c + 2] = u2;                                   \
            sB[br * BSTRIDE + c + 3] = u3;                                   \
        }                                                                    \
    } while (0)

    LDG_CHUNK(0);

    for (int c = 0; c < IN_F / 32; c++) {
        __syncthreads();
        STS_CHUNK();
        if (c < IN_F / 32 - 1)
            LDG_CHUNK((c + 1) * 32);
        __syncthreads();

#pragma unroll
        for (int ks = 0; ks < 4; ks++) {
            const int kb = ks * 8;
            const int arow = warp * 16 + g;
            uint32_t a0 = sA[(arow    ) * ASTRIDE + kb + t    ];
            uint32_t a1 = sA[(arow + 8) * ASTRIDE + kb + t    ];
            uint32_t a2 = sA[(arow    ) * ASTRIDE + kb + t + 4];
            uint32_t a3 = sA[(arow + 8) * ASTRIDE + kb + t + 4];
#pragma unroll
            for (int nt = 0; nt < 8; nt++) {
                uint32_t b0 = sB[(kb + t    ) * BSTRIDE + nt * 8 + g];
                uint32_t b1 = sB[(kb + t + 4) * BSTRIDE + nt * 8 + g];
                asm volatile(
                    "mma.sync.aligned.m16n8k8.row.col.f32.tf32.tf32.f32 "
                    "{%0,%1,%2,%3}, {%4,%5,%6,%7}, {%8,%9}, {%0,%1,%2,%3};"
                    : "+f"(acc[nt][0]), "+f"(acc[nt][1]),
                      "+f"(acc[nt][2]), "+f"(acc[nt][3])
                    : "r"(a0), "r"(a1), "r"(a2), "r"(a3), "r"(b0), "r"(b1));
            }
        }
    }

    // Epilogue: scale by norm[row], convert to fp16, store half2 pairs
    const int grow0 = row0 + warp * 16 + g;
    const int grow1 = grow0 + 8;
    const bool ok0 = (grow0 < N_NODES);
    const bool ok1 = (grow1 < N_NODES);
    const float nv0 = ok0 ? __ldg(norm + grow0) : 0.f;
    const float nv1 = ok1 ? __ldg(norm + grow1) : 0.f;
    __half2* __restrict__ hw2 = (__half2*)g_hw;   // 32 half2 per node row
#pragma unroll
    for (int nt = 0; nt < 8; nt++) {
        const int c2 = nt * 4 + t;                // half2 column index
        if (ok0)
            hw2[(size_t)grow0 * 32 + c2] =
                __floats2half2_rn(acc[nt][0] * nv0, acc[nt][1] * nv0);
        if (ok1)
            hw2[(size_t)grow1 * 32 + c2] =
                __floats2half2_rn(acc[nt][2] * nv1, acc[nt][3] * nv1);
    }
}

// ---------------------------------------------------------------------------
// Aggregate: 4 nodes per warp (two interleaved node-pairs), 16 lanes per node,
// each lane owns 4 halves (8 bytes) of the 128-byte fp16 node row.
// Accumulates in fp32.  Restores g_deg = 0 for the next kernel_launch call.
// ---------------------------------------------------------------------------
__global__ __launch_bounds__(256) void aggregate_kernel(
    const float* __restrict__ norm,
    const float* __restrict__ bias,
    float* __restrict__ out)
{
    const unsigned FULL = 0xFFFFFFFFu;
    const int wid  = (blockIdx.x * 256 + threadIdx.x) >> 5;
    const int base = wid * 4;
    if (base >= N_NODES) return;         // N_NODES % 4 == 0: uniform per warp
    const int lane = threadIdx.x & 31;
    const int half = lane >> 4;          // 0 or 1
    const int fl   = lane & 15;

    int st = 0, dg = 0;
    if (lane < 4) {
        st = g_start[base + lane];
        dg = g_deg[base + lane];
        g_deg[base + lane] = 0;          // restore invariant for next call
    }
    const int stA = __shfl_sync(FULL, st, half);
    const int dgA = __shfl_sync(FULL, dg, half);
    const int stB = __shfl_sync(FULL, st, 2 + half);
    const int dgB = __shfl_sync(FULL, dg, 2 + half);
    const int d0 = __shfl_sync(FULL, dg, 0), d1 = __shfl_sync(FULL, dg, 1);
    const int d2 = __shfl_sync(FULL, dg, 2), d3 = __shfl_sync(FULL, dg, 3);
    const int m = max(max(d0, d1), max(d2, d3));

    const uint2* __restrict__ hwq = (const uint2*)g_hw;  // 16 uint2 per row

    float4 aA = make_float4(0.f, 0.f, 0.f, 0.f);
    float4 aB = make_float4(0.f, 0.f, 0.f, 0.f);

    for (int b = 0; b < m; b += 16) {
        const int iA = (b + fl < dgA) ? __ldg(g_esrc + stA + b + fl) : 0;
        const int iB = (b + fl < dgB) ? __ldg(g_esrc + stB + b + fl) : 0;
#pragma unroll
        for (int j = 0; j < 16; j++) {
            const int sa = __shfl_sync(FULL, iA, (half << 4) + j);
            const int sb = __shfl_sync(FULL, iB, (half << 4) + j);
            if (b + j < dgA) {
                const uint2 v = __ldg(hwq + (size_t)sa * 16 + fl);
                const float2 p0 = __half22float2(*(const __half2*)&v.x);
                const float2 p1 = __half22float2(*(const __half2*)&v.y);
                aA.x += p0.x; aA.y += p0.y; aA.z += p1.x; aA.w += p1.y;
            }
            if (b + j < dgB) {
                const uint2 v = __ldg(hwq + (size_t)sb * 16 + fl);
                const float2 p0 = __half22float2(*(const __half2*)&v.x);
                const float2 p1 = __half22float2(*(const __half2*)&v.y);
                aB.x += p0.x; aB.y += p0.y; aB.z += p1.x; aB.w += p1.y;
            }
        }
    }

    const int nodeA = base + half;
    const int nodeB = base + 2 + half;
    const float nA = __ldg(norm + nodeA);
    const float nB = __ldg(norm + nodeB);
    const float4 bi = ((const float4*)bias)[fl];
    float4 rA, rB;
    rA.x = fmaxf(fmaf(aA.x, nA, bi.x), 0.f);
    rA.y = fmaxf(fmaf(aA.y, nA, bi.y), 0.f);
    rA.z = fmaxf(fmaf(aA.z, nA, bi.z), 0.f);
    rA.w = fmaxf(fmaf(aA.w, nA, bi.w), 0.f);
    rB.x = fmaxf(fmaf(aB.x, nB, bi.x), 0.f);
    rB.y = fmaxf(fmaf(aB.y, nB, bi.y), 0.f);
    rB.z = fmaxf(fmaf(aB.z, nB, bi.z), 0.f);
    rB.w = fmaxf(fmaf(aB.w, nB, bi.w), 0.f);
    ((float4*)out)[(size_t)nodeA * 16 + fl] = rA;
    ((float4*)out)[(size_t)nodeB * 16 + fl] = rB;
}

// ---------------------------------------------------------------------------
extern "C" void kernel_launch(void* const* d_in, const int* in_sizes, int n_in,
                              void* d_out, int out_size)
{
    const float* h      = (const float*)d_in[0];
    const float* norm   = (const float*)d_in[1];
    const int*   src    = (const int*)d_in[2];
    const int*   dst    = (const int*)d_in[3];
    const float* weight = (const float*)d_in[4];
    const float* bias   = (const float*)d_in[5];
    float* out = (float*)d_out;

    static cudaStream_t sB = nullptr;
    static cudaEvent_t  evFork = nullptr, evJoin = nullptr;
    if (sB == nullptr) {
        cudaStreamCreateWithFlags(&sB, cudaStreamNonBlocking);
        cudaEventCreateWithFlags(&evFork, cudaEventDisableTiming);
        cudaEventCreateWithFlags(&evJoin, cudaEventDisableTiming);
        cudaFuncSetAttribute(scan_kernel,
                             cudaFuncAttributeMaxDynamicSharedMemorySize,
                             SCAN_SMEM);
    }

    // Fork: CSR build on side stream, concurrent with the GEMM.
    cudaEventRecord(evFork, 0);
    cudaStreamWaitEvent(sB, evFork, 0);
    hist_kernel<<<(E4 + 255) / 256, 256, 0, sB>>>((const int4*)dst);
    scan_kernel<<<1, 1024, SCAN_SMEM, sB>>>();
    fill_kernel<<<(E4 + 255) / 256, 256, 0, sB>>>((const int4*)src,
                                                  (const int4*)dst);
    cudaEventRecord(evJoin, sB);

    // GEMM on the main stream (concurrent with CSR build).
    gemm_tf32_kernel<<<GEMM_BLOCKS, 256>>>(h, weight, norm);

    // Join, then aggregate (+ fused norm/bias/relu epilogue).
    cudaStreamWaitEvent(0, evJoin, 0);
    {
        const int warps  = N_NODES / 4;          // 12500
        const int blocks = (warps * 32 + 255) / 256;
        aggregate_kernel<<<blocks, 256>>>(norm, bias, out);
    }
}

// round 8
// speedup vs baseline: 1.9114x; 1.0071x over previous
#include <cuda_runtime.h>
#include <cuda_fp16.h>
#include <cstdint>

#define N_NODES 50000
#define N_EDGES 800000
#define IN_F    256
#define OUT_F   64
#define N_PAD   50176      // 1024 * 49, padded node count for the scan
#define SCAN_SMEM (N_PAD * 4)
#define E4 (N_EDGES / 4)   // 200000
#define GEMM_BLOCKS 391    // ceil(50000/128)
#define SAH 40             // sA stride in halves (32 + 8 pad) -> LDSM conflict-free
#define SBH 40             // sB stride in halves

// Scratch (device globals: allocation-guard compliant, zero-init at load)
__device__ __half g_hw[(size_t)N_NODES * OUT_F];  // projected*norm feats (fp16)
__device__ int    g_deg[N_NODES];                 // in-degree (zeroed by aggregate)
__device__ int    g_start[N_NODES];               // CSR row starts
__device__ int    g_slot[N_EDGES];                // per-edge slot within dst bucket
__device__ int    g_esrc[N_EDGES];                // src ids bucketed by dst

// ---------------------------------------------------------------------------
// Histogram + slot recording (side stream, concurrent with GEMM)
// ---------------------------------------------------------------------------
__global__ __launch_bounds__(256) void hist_kernel(const int4* __restrict__ dst4) {
    const int i = blockIdx.x * 256 + threadIdx.x;
    if (i >= E4) return;
    const int4 d = __ldg(dst4 + i);
    int4 sl;
    sl.x = atomicAdd(&g_deg[d.x], 1);
    sl.y = atomicAdd(&g_deg[d.y], 1);
    sl.z = atomicAdd(&g_deg[d.z], 1);
    sl.w = atomicAdd(&g_deg[d.w], 1);
    ((int4*)g_slot)[i] = sl;
}

// ---------------------------------------------------------------------------
// Single-block exclusive scan of g_deg -> g_start
// ---------------------------------------------------------------------------
__global__ __launch_bounds__(1024) void scan_kernel() {
    extern __shared__ int sh[];          // N_PAD ints
    __shared__ int ssum[1024];
    const int t = threadIdx.x;

    for (int i = t; i < N_PAD; i += 1024)
        sh[i] = (i < N_NODES) ? g_deg[i] : 0;
    __syncthreads();

    const int base = t * 49;
    int s = 0;
#pragma unroll
    for (int i = 0; i < 49; i++) s += sh[base + i];
    ssum[t] = s;
    __syncthreads();

    for (int off = 1; off < 1024; off <<= 1) {
        int x = (t >= off) ? ssum[t - off] : 0;
        __syncthreads();
        ssum[t] += x;
        __syncthreads();
    }

    int run = ssum[t] - s;
#pragma unroll
    for (int i = 0; i < 49; i++) {
        int v = sh[base + i];
        sh[base + i] = run;
        run += v;
    }
    __syncthreads();

    for (int i = t; i < N_NODES; i += 1024)
        g_start[i] = sh[i];
}

// ---------------------------------------------------------------------------
// Atomic-free fill: g_esrc[g_start[dst] + slot] = src   (4 edges per thread)
// ---------------------------------------------------------------------------
__global__ __launch_bounds__(256) void fill_kernel(
    const int4* __restrict__ src4,
    const int4* __restrict__ dst4)
{
    const int i = blockIdx.x * 256 + threadIdx.x;
    if (i >= E4) return;
    const int4 d  = __ldg(dst4 + i);
    const int4 sl = ((const int4*)g_slot)[i];
    const int4 s  = __ldg(src4 + i);
    g_esrc[g_start[d.x] + sl.x] = s.x;
    g_esrc[g_start[d.y] + sl.y] = s.y;
    g_esrc[g_start[d.z] + sl.z] = s.z;
    g_esrc[g_start[d.w] + sl.w] = s.w;
}

// ---------------------------------------------------------------------------
// fp16 tensor-core GEMM + fold norm:  g_hw[n,:] = fp16( (h[n,:] @ W) * norm[n] )
// 128 rows x 64 cols per block, 256 threads, K chunked by 32.
// mma.m16n8k16.f16 (fp32 accum); ALL fragment loads via ldmatrix.x4:
// per chunk each lane issues 2 A-LDSM + 8 B-LDSM + 16 MMA (vs 80 LDS before).
// B staged transposed [n][k] so k-pairs are contiguous 32-bit words.
// ---------------------------------------------------------------------------
__global__ __launch_bounds__(256, 3) void gemm_f16_kernel(
    const float* __restrict__ h,
    const float* __restrict__ w,
    const float* __restrict__ norm)
{
    __shared__ alignas(16) __half sA[128 * SAH];
    __shared__ alignas(16) __half sB[64 * SBH];

    const int tid  = threadIdx.x;
    const int warp = tid >> 5;
    const int lane = tid & 31;
    const int g    = lane >> 2;
    const int t    = lane & 3;
    const int row0 = blockIdx.x * 128;

    // staging coordinates
    const int ar = tid >> 1;            // A row 0..127 (2 threads/row)
    const int ap = tid & 1;             // 16-float half-row
    const bool aok = (row0 + ar) < N_NODES;
    const float* aptr = h + (size_t)(row0 + ar) * IN_F + ap * 16;
    const int bk = tid >> 3;            // w k-row 0..31 (8 threads/row)
    const int bn = tid & 7;             // 8-float n segment
    const float* bptr = w + (size_t)bk * OUT_F + bn * 8;

    // ldmatrix lane addresses (byte offsets into shared)
    const uint32_t sA_u = (uint32_t)__cvta_generic_to_shared(sA);
    const uint32_t sB_u = (uint32_t)__cvta_generic_to_shared(sB);
    // A tile x4: r0/r1 = rows g / g+8 (k lo), r2/r3 = same rows (k hi)
    const uint32_t aAddr = sA_u +
        (uint32_t)(((warp * 16 + ((lane >> 3) & 1) * 8 + (lane & 7)) * SAH +
                    (lane >> 4) * 8) * 2);
    // B tile x4 (per np): r0/r1 = n-rows np*16..+7 (k lo / k hi), r2/r3 = +8
    const uint32_t bRow = (uint32_t)((lane >> 4) * 8 + (lane & 7));
    const uint32_t bCol = (uint32_t)(((lane >> 3) & 1) * 8);

    float acc[8][4];
#pragma unroll
    for (int i = 0; i < 8; i++)
#pragma unroll
        for (int j = 0; j < 4; j++) acc[i][j] = 0.f;

    float4 aR[4];
    float4 bR[2];

#define LDG_CHUNK(kk)                                                        \
    do {                                                                     \
        _Pragma("unroll")                                                    \
        for (int i = 0; i < 4; i++)                                          \
            aR[i] = aok ? *(const float4*)(aptr + (kk) + i * 4)              \
                        : make_float4(0.f, 0.f, 0.f, 0.f);                   \
        _Pragma("unroll")                                                    \
        for (int i = 0; i < 2; i++)                                          \
            bR[i] = *(const float4*)(bptr + (size_t)(kk) * OUT_F + i * 4);   \
    } while (0)

    LDG_CHUNK(0);

    for (int c = 0; c < IN_F / 32; c++) {
        __syncthreads();
        // ---- stage A (convert to fp16, 8-byte stores)
#pragma unroll
        for (int i = 0; i < 4; i++) {
            __half2 h0 = __floats2half2_rn(aR[i].x, aR[i].y);
            __half2 h1 = __floats2half2_rn(aR[i].z, aR[i].w);
            uint2 u;
            u.x = *(uint32_t*)&h0;
            u.y = *(uint32_t*)&h1;
            *(uint2*)(sA + ar * SAH + ap * 16 + i * 4) = u;
        }
        // ---- stage B transposed: sB[n][k]
#pragma unroll
        for (int i = 0; i < 2; i++) {
            const int n0 = bn * 8 + i * 4;
            sB[(n0 + 0) * SBH + bk] = __float2half_rn(bR[i].x);
            sB[(n0 + 1) * SBH + bk] = __float2half_rn(bR[i].y);
            sB[(n0 + 2) * SBH + bk] = __float2half_rn(bR[i].z);
            sB[(n0 + 3) * SBH + bk] = __float2half_rn(bR[i].w);
        }
        if (c < IN_F / 32 - 1)
            LDG_CHUNK((c + 1) * 32);
        __syncthreads();

#pragma unroll
        for (int ks = 0; ks < 2; ks++) {
            uint32_t a0, a1, a2, a3;
            asm volatile(
                "ldmatrix.sync.aligned.m8n8.x4.shared.b16 {%0,%1,%2,%3}, [%4];"
                : "=r"(a0), "=r"(a1), "=r"(a2), "=r"(a3)
                : "r"(aAddr + ks * 32));
#pragma unroll
            for (int np = 0; np < 4; np++) {
                uint32_t b0, b1, b2, b3;
                const uint32_t bAddr = sB_u +
                    ((np * 16 + bRow) * SBH + ks * 16 + bCol) * 2;
                asm volatile(
                    "ldmatrix.sync.aligned.m8n8.x4.shared.b16 {%0,%1,%2,%3}, [%4];"
                    : "=r"(b0), "=r"(b1), "=r"(b2), "=r"(b3)
                    : "r"(bAddr));
                asm volatile(
                    "mma.sync.aligned.m16n8k16.row.col.f32.f16.f16.f32 "
                    "{%0,%1,%2,%3}, {%4,%5,%6,%7}, {%8,%9}, {%0,%1,%2,%3};"
                    : "+f"(acc[np * 2][0]), "+f"(acc[np * 2][1]),
                      "+f"(acc[np * 2][2]), "+f"(acc[np * 2][3])
                    : "r"(a0), "r"(a1), "r"(a2), "r"(a3), "r"(b0), "r"(b1));
                asm volatile(
                    "mma.sync.aligned.m16n8k16.row.col.f32.f16.f16.f32 "
                    "{%0,%1,%2,%3}, {%4,%5,%6,%7}, {%8,%9}, {%0,%1,%2,%3};"
                    : "+f"(acc[np * 2 + 1][0]), "+f"(acc[np * 2 + 1][1]),
                      "+f"(acc[np * 2 + 1][2]), "+f"(acc[np * 2 + 1][3])
                    : "r"(a0), "r"(a1), "r"(a2), "r"(a3), "r"(b2), "r"(b3));
            }
        }
    }

    // Epilogue: scale by norm[row], convert to fp16, store half2 pairs
    const int grow0 = row0 + warp * 16 + g;
    const int grow1 = grow0 + 8;
    const bool ok0 = (grow0 < N_NODES);
    const bool ok1 = (grow1 < N_NODES);
    const float nv0 = ok0 ? __ldg(norm + grow0) : 0.f;
    const float nv1 = ok1 ? __ldg(norm + grow1) : 0.f;
    __half2* __restrict__ hw2 = (__half2*)g_hw;   // 32 half2 per node row
#pragma unroll
    for (int nt = 0; nt < 8; nt++) {
        const int c2 = nt * 4 + t;                // half2 column index
        if (ok0)
            hw2[(size_t)grow0 * 32 + c2] =
                __floats2half2_rn(acc[nt][0] * nv0, acc[nt][1] * nv0);
        if (ok1)
            hw2[(size_t)grow1 * 32 + c2] =
                __floats2half2_rn(acc[nt][2] * nv1, acc[nt][3] * nv1);
    }
}

// ---------------------------------------------------------------------------
// Aggregate: 4 nodes per warp (two interleaved node-pairs), 16 lanes per node,
// each lane owns 4 halves (8 bytes) of the 128-byte fp16 node row.
// Accumulates in fp32.  Restores g_deg = 0 for the next kernel_launch call.
// ---------------------------------------------------------------------------
__global__ __launch_bounds__(256) void aggregate_kernel(
    const float* __restrict__ norm,
    const float* __restrict__ bias,
    float* __restrict__ out)
{
    const unsigned FULL = 0xFFFFFFFFu;
    const int wid  = (blockIdx.x * 256 + threadIdx.x) >> 5;
    const int base = wid * 4;
    if (base >= N_NODES) return;         // N_NODES % 4 == 0: uniform per warp
    const int lane = threadIdx.x & 31;
    const int half = lane >> 4;          // 0 or 1
    const int fl   = lane & 15;

    int st = 0, dg = 0;
    if (lane < 4) {
        st = g_start[base + lane];
        dg = g_deg[base + lane];
        g_deg[base + lane] = 0;          // restore invariant for next call
    }
    const int stA = __shfl_sync(FULL, st, half);
    const int dgA = __shfl_sync(FULL, dg, half);
    const int stB = __shfl_sync(FULL, st, 2 + half);
    const int dgB = __shfl_sync(FULL, dg, 2 + half);
    const int d0 = __shfl_sync(FULL, dg, 0), d1 = __shfl_sync(FULL, dg, 1);
    const int d2 = __shfl_sync(FULL, dg, 2), d3 = __shfl_sync(FULL, dg, 3);
    const int m = max(max(d0, d1), max(d2, d3));

    const uint2* __restrict__ hwq = (const uint2*)g_hw;  // 16 uint2 per row

    float4 aA = make_float4(0.f, 0.f, 0.f, 0.f);
    float4 aB = make_float4(0.f, 0.f, 0.f, 0.f);

    for (int b = 0; b < m; b += 16) {
        const int iA = (b + fl < dgA) ? __ldg(g_esrc + stA + b + fl) : 0;
        const int iB = (b + fl < dgB) ? __ldg(g_esrc + stB + b + fl) : 0;
#pragma unroll
        for (int j = 0; j < 16; j++) {
            const int sa = __shfl_sync(FULL, iA, (half << 4) + j);
            const int sb = __shfl_sync(FULL, iB, (half << 4) + j);
            if (b + j < dgA) {
                const uint2 v = __ldg(hwq + (size_t)sa * 16 + fl);
                const float2 p0 = __half22float2(*(const __half2*)&v.x);
                const float2 p1 = __half22float2(*(const __half2*)&v.y);
                aA.x += p0.x; aA.y += p0.y; aA.z += p1.x; aA.w += p1.y;
            }
            if (b + j < dgB) {
                const uint2 v = __ldg(hwq + (size_t)sb * 16 + fl);
                const float2 p0 = __half22float2(*(const __half2*)&v.x);
                const float2 p1 = __half22float2(*(const __half2*)&v.y);
                aB.x += p0.x; aB.y += p0.y; aB.z += p1.x; aB.w += p1.y;
            }
        }
    }

    const int nodeA = base + half;
    const int nodeB = base + 2 + half;
    const float nA = __ldg(norm + nodeA);
    const float nB = __ldg(norm + nodeB);
    const float4 bi = ((const float4*)bias)[fl];
    float4 rA, rB;
    rA.x = fmaxf(fmaf(aA.x, nA, bi.x), 0.f);
    rA.y = fmaxf(fmaf(aA.y, nA, bi.y), 0.f);
    rA.z = fmaxf(fmaf(aA.z, nA, bi.z), 0.f);
    rA.w = fmaxf(fmaf(aA.w, nA, bi.w), 0.f);
    rB.x = fmaxf(fmaf(aB.x, nB, bi.x), 0.f);
    rB.y = fmaxf(fmaf(aB.y, nB, bi.y), 0.f);
    rB.z = fmaxf(fmaf(aB.z, nB, bi.z), 0.f);
    rB.w = fmaxf(fmaf(aB.w, nB, bi.w), 0.f);
    ((float4*)out)[(size_t)nodeA * 16 + fl] = rA;
    ((float4*)out)[(size_t)nodeB * 16 + fl] = rB;
}

// ---------------------------------------------------------------------------
extern "C" void kernel_launch(void* const* d_in, const int* in_sizes, int n_in,
                              void* d_out, int out_size)
{
    const float* h      = (const float*)d_in[0];
    const float* norm   = (const float*)d_in[1];
    const int*   src    = (const int*)d_in[2];
    const int*   dst    = (const int*)d_in[3];
    const float* weight = (const float*)d_in[4];
    const float* bias   = (const float*)d_in[5];
    float* out = (float*)d_out;

    static cudaStream_t sB = nullptr;
    static cudaEvent_t  evFork = nullptr, evJoin = nullptr;
    if (sB == nullptr) {
        cudaStreamCreateWithFlags(&sB, cudaStreamNonBlocking);
        cudaEventCreateWithFlags(&evFork, cudaEventDisableTiming);
        cudaEventCreateWithFlags(&evJoin, cudaEventDisableTiming);
        cudaFuncSetAttribute(scan_kernel,
                             cudaFuncAttributeMaxDynamicSharedMemorySize,
                             SCAN_SMEM);
    }

    // Fork: CSR build on side stream, concurrent with the GEMM.
    cudaEventRecord(evFork, 0);
    cudaStreamWaitEvent(sB, evFork, 0);
    hist_kernel<<<(E4 + 255) / 256, 256, 0, sB>>>((const int4*)dst);
    scan_kernel<<<1, 1024, SCAN_SMEM, sB>>>();
    fill_kernel<<<(E4 + 255) / 256, 256, 0, sB>>>((const int4*)src,
                                                  (const int4*)dst);
    cudaEventRecord(evJoin, sB);

    // GEMM on the main stream (concurrent with CSR build).
    gemm_f16_kernel<<<GEMM_BLOCKS, 256>>>(h, weight, norm);

    // Join, then aggregate (+ fused norm/bias/relu epilogue).
    cudaStreamWaitEvent(0, evJoin, 0);
    {
        const int warps  = N_NODES / 4;          // 12500
        const int blocks = (warps * 32 + 255) / 256;
        aggregate_kernel<<<blocks, 256>>>(norm, bias, out);
    }
}

// round 10
// speedup vs baseline: 2.0045x; 1.0487x over previous
#include <cuda_runtime.h>
#include <cuda_fp16.h>
#include <cstdint>

#define N_NODES 50000
#define N_EDGES 800000
#define IN_F    256
#define OUT_F   64
#define N_PAD   50176      // 1024 * 49, padded node count for the scan
#define SCAN_SMEM (N_PAD * 4)
#define E4 (N_EDGES / 4)   // 200000
#define GEMM_BLOCKS 391    // ceil(50000/128)
#define SBH 264            // sB stride in halves (256 + 8) -> LDSM conflict-free

// Scratch (device globals: allocation-guard compliant, zero-init at load)
__device__ __half g_hw[(size_t)N_NODES * OUT_F];  // projected*norm feats (fp16)
__device__ int    g_deg[N_NODES];                 // in-degree (zeroed by aggregate)
__device__ int    g_start[N_NODES];               // CSR row starts
__device__ int    g_slot[N_EDGES];                // per-edge slot within dst bucket
__device__ int    g_esrc[N_EDGES];                // src ids bucketed by dst

// ---------------------------------------------------------------------------
// Histogram + slot recording (side stream, concurrent with GEMM)
// ---------------------------------------------------------------------------
__global__ __launch_bounds__(256) void hist_kernel(const int4* __restrict__ dst4) {
    const int i = blockIdx.x * 256 + threadIdx.x;
    if (i >= E4) return;
    const int4 d = __ldg(dst4 + i);
    int4 sl;
    sl.x = atomicAdd(&g_deg[d.x], 1);
    sl.y = atomicAdd(&g_deg[d.y], 1);
    sl.z = atomicAdd(&g_deg[d.z], 1);
    sl.w = atomicAdd(&g_deg[d.w], 1);
    ((int4*)g_slot)[i] = sl;
}

// ---------------------------------------------------------------------------
// Single-block exclusive scan of g_deg -> g_start
// ---------------------------------------------------------------------------
__global__ __launch_bounds__(1024) void scan_kernel() {
    extern __shared__ int sh[];          // N_PAD ints
    __shared__ int ssum[1024];
    const int t = threadIdx.x;

    for (int i = t; i < N_PAD; i += 1024)
        sh[i] = (i < N_NODES) ? g_deg[i] : 0;
    __syncthreads();

    const int base = t * 49;
    int s = 0;
#pragma unroll
    for (int i = 0; i < 49; i++) s += sh[base + i];
    ssum[t] = s;
    __syncthreads();

    for (int off = 1; off < 1024; off <<= 1) {
        int x = (t >= off) ? ssum[t - off] : 0;
        __syncthreads();
        ssum[t] += x;
        __syncthreads();
    }

    int run = ssum[t] - s;
#pragma unroll
    for (int i = 0; i < 49; i++) {
        int v = sh[base + i];
        sh[base + i] = run;
        run += v;
    }
    __syncthreads();

    for (int i = t; i < N_NODES; i += 1024)
        g_start[i] = sh[i];
}

// ---------------------------------------------------------------------------
// Atomic-free fill: g_esrc[g_start[dst] + slot] = src   (4 edges per thread)
// ---------------------------------------------------------------------------
__global__ __launch_bounds__(256) void fill_kernel(
    const int4* __restrict__ src4,
    const int4* __restrict__ dst4)
{
    const int i = blockIdx.x * 256 + threadIdx.x;
    if (i >= E4) return;
    const int4 d  = __ldg(dst4 + i);
    const int4 sl = ((const int4*)g_slot)[i];
    const int4 s  = __ldg(src4 + i);
    g_esrc[g_start[d.x] + sl.x] = s.x;
    g_esrc[g_start[d.y] + sl.y] = s.y;
    g_esrc[g_start[d.z] + sl.z] = s.z;
    g_esrc[g_start[d.w] + sl.w] = s.w;
}

// ---------------------------------------------------------------------------
// fp16 GEMM + fold norm, streaming A:  g_hw[n,:] = fp16((h[n,:] @ W) * norm[n])
// Per block: 128 rows x 64 cols.  W staged ONCE to smem (fp16, [n][k] + pad);
// A fragments loaded straight from global (LDG.64 + pack), depth-2 register
// prefetch, NO barriers in the mainloop.
// B ldmatrix lane mapping restored to the round-8 VALIDATED form:
//   bRow keyed on bit4 (n-halves), bCol keyed on bit3 (k-halves) so that
//   {b0,b1} = n0-7 x {k-lo,k-hi} and {b2,b3} = n8-15 x {k-lo,k-hi}.
// ---------------------------------------------------------------------------
__global__ __launch_bounds__(256, 3) void gemm_f16_kernel(
    const float* __restrict__ h,
    const float* __restrict__ w,
    const float* __restrict__ norm)
{
    __shared__ alignas(16) __half sB[64 * SBH];

    const int tid  = threadIdx.x;
    const int warp = tid >> 5;
    const int lane = tid & 31;
    const int g    = lane >> 2;
    const int t    = lane & 3;
    const int row0 = blockIdx.x * 128;

    // ---- stage full W once: w[k][n] (f32) -> sB[n][k] (f16)
#pragma unroll
    for (int i = 0; i < 16; i++) {
        const int fid = tid + 256 * i;        // float4 id, 0..4095
        const int k   = fid >> 4;             // 0..255
        const int n0  = (fid & 15) * 4;
        const float4 v = __ldg((const float4*)w + fid);
        sB[(n0 + 0) * SBH + k] = __float2half_rn(v.x);
        sB[(n0 + 1) * SBH + k] = __float2half_rn(v.y);
        sB[(n0 + 2) * SBH + k] = __float2half_rn(v.z);
        sB[(n0 + 3) * SBH + k] = __float2half_rn(v.w);
    }
    __syncthreads();

    // ---- per-lane A row pointers (m16n8k16 fragment layout)
    const int r0 = row0 + warp * 16 + g;      // rows 0-7 of warp tile
    const int r1 = r0 + 8;                    // rows 8-15
    const bool ok0 = (r0 < N_NODES);
    const bool ok1 = (r1 < N_NODES);
    const float* pA0 = h + (size_t)r0 * IN_F + 2 * t;
    const float* pA1 = h + (size_t)r1 * IN_F + 2 * t;

    // ---- B ldmatrix lane addresses (round-8 validated mapping)
    const uint32_t sB_u = (uint32_t)__cvta_generic_to_shared(sB);
    const uint32_t bRow = (uint32_t)((lane >> 4) * 8 + (lane & 7));
    const uint32_t bCol = (uint32_t)(((lane >> 3) & 1) * 8);
    uint32_t bAddr[4];
#pragma unroll
    for (int np = 0; np < 4; np++)
        bAddr[np] = sB_u + ((np * 16 + bRow) * SBH + bCol) * 2;

    float acc[8][4];
#pragma unroll
    for (int i = 0; i < 8; i++)
#pragma unroll
        for (int j = 0; j < 4; j++) acc[i][j] = 0.f;

    const float2 z2 = make_float2(0.f, 0.f);
    float2 fA[2][4];

#define LDG_A(buf, s)                                                        \
    do {                                                                     \
        const int kb = (s) * 16;                                             \
        fA[buf][0] = ok0 ? __ldg((const float2*)(pA0 + kb    )) : z2;        \
        fA[buf][1] = ok1 ? __ldg((const float2*)(pA1 + kb    )) : z2;        \
        fA[buf][2] = ok0 ? __ldg((const float2*)(pA0 + kb + 8)) : z2;        \
        fA[buf][3] = ok1 ? __ldg((const float2*)(pA1 + kb + 8)) : z2;        \
    } while (0)

    LDG_A(0, 0);
    LDG_A(1, 1);

#pragma unroll
    for (int s = 0; s < 16; s++) {
        const int buf = s & 1;
        uint32_t a[4];
#pragma unroll
        for (int i = 0; i < 4; i++) {
            __half2 hh = __floats2half2_rn(fA[buf][i].x, fA[buf][i].y);
            a[i] = *(uint32_t*)&hh;
        }
        if (s < 14) LDG_A(buf, s + 2);

#pragma unroll
        for (int np = 0; np < 4; np++) {
            uint32_t b0, b1, b2, b3;
            asm volatile(
                "ldmatrix.sync.aligned.m8n8.x4.shared.b16 {%0,%1,%2,%3}, [%4];"
                : "=r"(b0), "=r"(b1), "=r"(b2), "=r"(b3)
                : "r"(bAddr[np] + s * 32));
            asm volatile(
                "mma.sync.aligned.m16n8k16.row.col.f32.f16.f16.f32 "
                "{%0,%1,%2,%3}, {%4,%5,%6,%7}, {%8,%9}, {%0,%1,%2,%3};"
                : "+f"(acc[np * 2][0]), "+f"(acc[np * 2][1]),
                  "+f"(acc[np * 2][2]), "+f"(acc[np * 2][3])
                : "r"(a[0]), "r"(a[1]), "r"(a[2]), "r"(a[3]), "r"(b0), "r"(b1));
            asm volatile(
                "mma.sync.aligned.m16n8k16.row.col.f32.f16.f16.f32 "
                "{%0,%1,%2,%3}, {%4,%5,%6,%7}, {%8,%9}, {%0,%1,%2,%3};"
                : "+f"(acc[np * 2 + 1][0]), "+f"(acc[np * 2 + 1][1]),
                  "+f"(acc[np * 2 + 1][2]), "+f"(acc[np * 2 + 1][3])
                : "r"(a[0]), "r"(a[1]), "r"(a[2]), "r"(a[3]), "r"(b2), "r"(b3));
        }
    }

    // Epilogue: scale by norm[row], convert to fp16, store half2 pairs
    const float nv0 = ok0 ? __ldg(norm + r0) : 0.f;
    const float nv1 = ok1 ? __ldg(norm + r1) : 0.f;
    __half2* __restrict__ hw2 = (__half2*)g_hw;   // 32 half2 per node row
#pragma unroll
    for (int nt = 0; nt < 8; nt++) {
        const int c2 = nt * 4 + t;                // half2 column index
        if (ok0)
            hw2[(size_t)r0 * 32 + c2] =
                __floats2half2_rn(acc[nt][0] * nv0, acc[nt][1] * nv0);
        if (ok1)
            hw2[(size_t)r1 * 32 + c2] =
                __floats2half2_rn(acc[nt][2] * nv1, acc[nt][3] * nv1);
    }
}

// ---------------------------------------------------------------------------
// Aggregate: 4 nodes per warp (two interleaved node-pairs), 16 lanes per node,
// each lane owns 4 halves (8 bytes) of the 128-byte fp16 node row.
// Accumulates in fp32.  Restores g_deg = 0 for the next kernel_launch call.
// ---------------------------------------------------------------------------
__global__ __launch_bounds__(256) void aggregate_kernel(
    const float* __restrict__ norm,
    const float* __restrict__ bias,
    float* __restrict__ out)
{
    const unsigned FULL = 0xFFFFFFFFu;
    const int wid  = (blockIdx.x * 256 + threadIdx.x) >> 5;
    const int base = wid * 4;
    if (base >= N_NODES) return;         // N_NODES % 4 == 0: uniform per warp
    const int lane = threadIdx.x & 31;
    const int half = lane >> 4;          // 0 or 1
    const int fl   = lane & 15;

    int st = 0, dg = 0;
    if (lane < 4) {
        st = g_start[base + lane];
        dg = g_deg[base + lane];
        g_deg[base + lane] = 0;          // restore invariant for next call
    }
    const int stA = __shfl_sync(FULL, st, half);
    const int dgA = __shfl_sync(FULL, dg, half);
    const int stB = __shfl_sync(FULL, st, 2 + half);
    const int dgB = __shfl_sync(FULL, dg, 2 + half);
    const int d0 = __shfl_sync(FULL, dg, 0), d1 = __shfl_sync(FULL, dg, 1);
    const int d2 = __shfl_sync(FULL, dg, 2), d3 = __shfl_sync(FULL, dg, 3);
    const int m = max(max(d0, d1), max(d2, d3));

    const uint2* __restrict__ hwq = (const uint2*)g_hw;  // 16 uint2 per row

    float4 aA = make_float4(0.f, 0.f, 0.f, 0.f);
    float4 aB = make_float4(0.f, 0.f, 0.f, 0.f);

    for (int b = 0; b < m; b += 16) {
        const int iA = (b + fl < dgA) ? __ldg(g_esrc + stA + b + fl) : 0;
        const int iB = (b + fl < dgB) ? __ldg(g_esrc + stB + b + fl) : 0;
#pragma unroll
        for (int j = 0; j < 16; j++) {
            const int sa = __shfl_sync(FULL, iA, (half << 4) + j);
            const int sb = __shfl_sync(FULL, iB, (half << 4) + j);
            if (b + j < dgA) {
                const uint2 v = __ldg(hwq + (size_t)sa * 16 + fl);
                const float2 p0 = __half22float2(*(const __half2*)&v.x);
                const float2 p1 = __half22float2(*(const __half2*)&v.y);
                aA.x += p0.x; aA.y += p0.y; aA.z += p1.x; aA.w += p1.y;
            }
            if (b + j < dgB) {
                const uint2 v = __ldg(hwq + (size_t)sb * 16 + fl);
                const float2 p0 = __half22float2(*(const __half2*)&v.x);
                const float2 p1 = __half22float2(*(const __half2*)&v.y);
                aB.x += p0.x; aB.y += p0.y; aB.z += p1.x; aB.w += p1.y;
            }
        }
    }

    const int nodeA = base + half;
    const int nodeB = base + 2 + half;
    const float nA = __ldg(norm + nodeA);
    const float nB = __ldg(norm + nodeB);
    const float4 bi = ((const float4*)bias)[fl];
    float4 rA, rB;
    rA.x = fmaxf(fmaf(aA.x, nA, bi.x), 0.f);
    rA.y = fmaxf(fmaf(aA.y, nA, bi.y), 0.f);
    rA.z = fmaxf(fmaf(aA.z, nA, bi.z), 0.f);
    rA.w = fmaxf(fmaf(aA.w, nA, bi.w), 0.f);
    rB.x = fmaxf(fmaf(aB.x, nB, bi.x), 0.f);
    rB.y = fmaxf(fmaf(aB.y, nB, bi.y), 0.f);
    rB.z = fmaxf(fmaf(aB.z, nB, bi.z), 0.f);
    rB.w = fmaxf(fmaf(aB.w, nB, bi.w), 0.f);
    ((float4*)out)[(size_t)nodeA * 16 + fl] = rA;
    ((float4*)out)[(size_t)nodeB * 16 + fl] = rB;
}

// ---------------------------------------------------------------------------
extern "C" void kernel_launch(void* const* d_in, const int* in_sizes, int n_in,
                              void* d_out, int out_size)
{
    const float* h      = (const float*)d_in[0];
    const float* norm   = (const float*)d_in[1];
    const int*   src    = (const int*)d_in[2];
    const int*   dst    = (const int*)d_in[3];
    const float* weight = (const float*)d_in[4];
    const float* bias   = (const float*)d_in[5];
    float* out = (float*)d_out;

    static cudaStream_t sB = nullptr;
    static cudaEvent_t  evFork = nullptr, evJoin = nullptr;
    if (sB == nullptr) {
        cudaStreamCreateWithFlags(&sB, cudaStreamNonBlocking);
        cudaEventCreateWithFlags(&evFork, cudaEventDisableTiming);
        cudaEventCreateWithFlags(&evJoin, cudaEventDisableTiming);
        cudaFuncSetAttribute(scan_kernel,
                             cudaFuncAttributeMaxDynamicSharedMemorySize,
                             SCAN_SMEM);
    }

    // Fork: CSR build on side stream, concurrent with the GEMM.
    cudaEventRecord(evFork, 0);
    cudaStreamWaitEvent(sB, evFork, 0);
    hist_kernel<<<(E4 + 255) / 256, 256, 0, sB>>>((const int4*)dst);
    scan_kernel<<<1, 1024, SCAN_SMEM, sB>>>();
    fill_kernel<<<(E4 + 255) / 256, 256, 0, sB>>>((const int4*)src,
                                                  (const int4*)dst);
    cudaEventRecord(evJoin, sB);

    // GEMM on the main stream (concurrent with CSR build).
    gemm_f16_kernel<<<GEMM_BLOCKS, 256>>>(h, weight, norm);

    // Join, then aggregate (+ fused norm/bias/relu epilogue).
    cudaStreamWaitEvent(0, evJoin, 0);
    {
        const int warps  = N_NODES / 4;          // 12500
        const int blocks = (warps * 32 + 255) / 256;
        aggregate_kernel<<<blocks, 256>>>(norm, bias, out);
    }
}